// round 1
// baseline (speedup 1.0000x reference)
#include <cuda_runtime.h>
#include <math.h>

// ---------------------------------------------------------------------------
// Problem constants: B=16, T=12, N=2048, D=128
//   x: [16,12,2048,128] f32
// ---------------------------------------------------------------------------

#define BMT 128
#define BNT 128
#define BKT 8
#define TMT 8
#define TNT 8

// -------------------- scratch arena (float elements) -----------------------
// XT  [B,N,T*D] 50331648   (aliased by U  [32768,1536])
// S   [16,2048,2048] 67108864 (aliased by ON [32768,1536] = 50331648)
// H1,Y,Q,K,V,O: 4194304 each
// HN  [B,T,N,D] 50331648   (aliased by GH [229376,128] = 29360128)
// RE,IM,MA,MB,MC,MD: 29360128 each
static const long long OFF_XT = 0;
static const long long OFF_S  = 50331648LL;
static const long long OFF_H1 = 117440512LL;
static const long long OFF_Y  = 121634816LL;
static const long long OFF_Q  = 125829120LL;
static const long long OFF_K  = 130023424LL;
static const long long OFF_V  = 134217728LL;
static const long long OFF_O  = 138412032LL;
static const long long OFF_HN = 142606336LL;
static const long long OFF_RE = 192937984LL;
static const long long OFF_IM = 222298112LL;
static const long long OFF_MA = 251658240LL;
static const long long OFF_MB = 281018368LL;
static const long long OFF_MC = 310378496LL;
static const long long OFF_MD = 339738624LL;

__device__ float g_arena[369098752];   // ~1.48 GB scratch

// -------------------- epilogue ----------------------------------------------
template <int EPI>
__device__ __forceinline__ float epi_f(float v) {
    if (EPI == 1) return v > 0.f ? v : 0.f;                                   // relu
    if (EPI == 2) return 0.5f * v * (1.f + erff(v * 0.7071067811865476f));    // exact gelu
    return v;
}

// -------------------- SGEMM: C = epi(alpha * A@op(B) + bias) ----------------
// A: [M,K] row-major.  BT=true: B is [N,K] (C = A*B^T).  BT=false: B is [K,N].
// Batched via blockIdx.z with element strides sA/sB/sC.
// Requires: M%128==0, N%128==0, K%8==0.
template <int EPI, bool BT>
__global__ void __launch_bounds__(256)
gemm_kernel(const float* __restrict__ A, const float* __restrict__ B,
            const float* __restrict__ bias, float* __restrict__ C,
            int M, int N, int K, float alpha,
            long long sA, long long sB, long long sC)
{
    __shared__ __align__(16) float As[BKT][BMT];
    __shared__ __align__(16) float Bs[BKT][BNT];

    const int tid = threadIdx.x;
    const int bx = blockIdx.x, by = blockIdx.y, bz = blockIdx.z;

    const float* Ap = A + (long long)bz * sA + (long long)by * BMT * K;
    const float* Bp;
    if (BT) Bp = B + (long long)bz * sB + (long long)bx * BNT * K;
    else    Bp = B + (long long)bz * sB + bx * BNT;
    float* Cp = C + (long long)bz * sC + (long long)by * BMT * N + bx * BNT;

    const int aRow = tid >> 1, aCol = (tid & 1) << 2;   // 128 x 8 tile, float4
    const int bRowN = tid >> 5, bColN = (tid & 31) << 2; // [K,N] loader

    const int tr = (tid >> 4) << 3;  // 16x16 thread grid, 8x8 microtile
    const int tc = (tid & 15) << 3;

    float acc[TMT][TNT];
    #pragma unroll
    for (int i = 0; i < TMT; i++)
        #pragma unroll
        for (int j = 0; j < TNT; j++) acc[i][j] = 0.f;

    for (int k0 = 0; k0 < K; k0 += BKT) {
        float4 av = *(const float4*)(Ap + (long long)aRow * K + k0 + aCol);
        As[aCol + 0][aRow] = av.x;
        As[aCol + 1][aRow] = av.y;
        As[aCol + 2][aRow] = av.z;
        As[aCol + 3][aRow] = av.w;
        if (BT) {
            float4 bv = *(const float4*)(Bp + (long long)aRow * K + k0 + aCol);
            Bs[aCol + 0][aRow] = bv.x;
            Bs[aCol + 1][aRow] = bv.y;
            Bs[aCol + 2][aRow] = bv.z;
            Bs[aCol + 3][aRow] = bv.w;
        } else {
            float4 bv = *(const float4*)(Bp + (long long)(k0 + bRowN) * N + bColN);
            *(float4*)&Bs[bRowN][bColN] = bv;
        }
        __syncthreads();

        #pragma unroll
        for (int kk = 0; kk < BKT; kk++) {
            float a[TMT], b[TNT];
            *(float4*)&a[0] = *(const float4*)&As[kk][tr];
            *(float4*)&a[4] = *(const float4*)&As[kk][tr + 4];
            *(float4*)&b[0] = *(const float4*)&Bs[kk][tc];
            *(float4*)&b[4] = *(const float4*)&Bs[kk][tc + 4];
            #pragma unroll
            for (int i = 0; i < TMT; i++)
                #pragma unroll
                for (int j = 0; j < TNT; j++)
                    acc[i][j] = fmaf(a[i], b[j], acc[i][j]);
        }
        __syncthreads();
    }

    float bvv[TNT];
    #pragma unroll
    for (int j = 0; j < TNT; j++)
        bvv[j] = bias ? bias[bx * BNT + tc + j] : 0.f;

    #pragma unroll
    for (int i = 0; i < TMT; i++) {
        float tmp[TNT];
        #pragma unroll
        for (int j = 0; j < TNT; j++)
            tmp[j] = epi_f<EPI>(acc[i][j] * alpha + bvv[j]);
        *(float4*)(Cp + (long long)(tr + i) * N + tc)     = *(float4*)&tmp[0];
        *(float4*)(Cp + (long long)(tr + i) * N + tc + 4) = *(float4*)&tmp[4];
    }
}

// -------------------- x [B,T,N,D] -> xt [B,N,T*D] ---------------------------
__global__ void transpose_xt(const float* __restrict__ x, float* __restrict__ xt) {
    int gid = blockIdx.x * 256 + threadIdx.x;        // < 786432*32
    int r = gid >> 5;                                // row in [0, B*T*N)
    int c = (gid & 31) << 2;
    int b = r / (12 * 2048);
    int rem = r - b * (12 * 2048);
    int t = rem >> 11;
    int n = rem & 2047;
    float4 v = *(const float4*)(x + (long long)r * 128 + c);
    *(float4*)(xt + ((long long)(b * 2048 + n) * 1536 + t * 128 + c)) = v;
}

// -------------------- row softmax (row length 2048) -------------------------
__global__ void softmax2048(float* __restrict__ S) {
    float* row = S + (long long)blockIdx.x * 2048;
    int t = threadIdx.x;
    float v[8];
    float mx = -3.4e38f;
    #pragma unroll
    for (int i = 0; i < 8; i++) { v[i] = row[t + (i << 8)]; mx = fmaxf(mx, v[i]); }
    __shared__ float red[8];
    #pragma unroll
    for (int o = 16; o; o >>= 1) mx = fmaxf(mx, __shfl_xor_sync(0xffffffffu, mx, o));
    if ((t & 31) == 0) red[t >> 5] = mx;
    __syncthreads();
    mx = red[0];
    #pragma unroll
    for (int i = 1; i < 8; i++) mx = fmaxf(mx, red[i]);
    float s = 0.f;
    #pragma unroll
    for (int i = 0; i < 8; i++) { v[i] = __expf(v[i] - mx); s += v[i]; }
    #pragma unroll
    for (int o = 16; o; o >>= 1) s += __shfl_xor_sync(0xffffffffu, s, o);
    __syncthreads();
    if ((t & 31) == 0) red[t >> 5] = s;
    __syncthreads();
    s = 0.f;
    #pragma unroll
    for (int i = 0; i < 8; i++) s += red[i];
    float inv = 1.f / s;
    #pragma unroll
    for (int i = 0; i < 8; i++) row[t + (i << 8)] = v[i] * inv;
}

// -------------------- residual + LayerNorm ----------------------------------
// ON: [B,N,T*D] (conv_up output), x/HN: [B,T,N,D]. One row (128) per block.
__global__ void resid_ln(const float* __restrict__ ON, const float* __restrict__ x,
                         const float* __restrict__ gamma, const float* __restrict__ beta,
                         float* __restrict__ HN)
{
    long long r = blockIdx.x;                      // < B*T*N = 786432
    int d = threadIdx.x;
    int b = (int)(r / 24576);
    int rem = (int)(r % 24576);
    int t = rem >> 11;
    int n = rem & 2047;
    float v = ON[((long long)(b * 2048 + n)) * 1536 + t * 128 + d] + x[r * 128 + d];
    float s = v, q = v * v;
    #pragma unroll
    for (int o = 16; o; o >>= 1) {
        s += __shfl_xor_sync(0xffffffffu, s, o);
        q += __shfl_xor_sync(0xffffffffu, q, o);
    }
    __shared__ float ss[4], qq[4];
    int w = d >> 5, lane = d & 31;
    if (lane == 0) { ss[w] = s; qq[w] = q; }
    __syncthreads();
    s = ss[0] + ss[1] + ss[2] + ss[3];
    q = qq[0] + qq[1] + qq[2] + qq[3];
    float mean = s * (1.f / 128.f);
    float var = q * (1.f / 128.f) - mean * mean;
    float rstd = rsqrtf(var + 1e-5f);
    HN[r * 128 + d] = (v - mean) * rstd * gamma[d] + beta[d];
}

// -------------------- 12-point rfft over time axis --------------------------
__global__ void dft12(const float* __restrict__ hn,
                      float* __restrict__ re, float* __restrict__ im)
{
    int idx = blockIdx.x * 256 + threadIdx.x;      // < B*N*D = 4194304
    int b = idx >> 18;
    int nd = idx & 262143;
    const float* p = hn + (long long)b * 12 * 262144 + nd;
    float vt[12];
    #pragma unroll
    for (int t = 0; t < 12; t++) vt[t] = p[(long long)t * 262144];
    const float CT[12] = {1.f, 0.8660254037844386f, 0.5f, 0.f, -0.5f, -0.8660254037844386f,
                          -1.f, -0.8660254037844386f, -0.5f, 0.f, 0.5f, 0.8660254037844386f};
    const float ST[12] = {0.f, 0.5f, 0.8660254037844386f, 1.f, 0.8660254037844386f, 0.5f,
                          0.f, -0.5f, -0.8660254037844386f, -1.f, -0.8660254037844386f, -0.5f};
    #pragma unroll
    for (int f = 0; f < 7; f++) {
        float sr = 0.f, si = 0.f;
        #pragma unroll
        for (int t = 0; t < 12; t++) {
            int k = (f * t) % 12;
            sr += vt[t] * CT[k];
            si -= vt[t] * ST[k];
        }
        long long o = ((long long)b * 7 + f) * 262144 + nd;
        re[o] = sr;
        im[o] = si;
    }
}

// -------------------- irfft(n=12) + residual --------------------------------
// hr = MA - MB, hi = MC + MD. Imag parts of bins 0 and 6 are ignored (c2r).
__global__ void irfft12(const float* __restrict__ MAp, const float* __restrict__ MBp,
                        const float* __restrict__ MCp, const float* __restrict__ MDp,
                        const float* __restrict__ x, float* __restrict__ out)
{
    int idx = blockIdx.x * 256 + threadIdx.x;      // < 4194304
    int b = idx >> 18;
    int nd = idx & 262143;
    float hr[7], hi[7];
    #pragma unroll
    for (int f = 0; f < 7; f++) {
        long long o = ((long long)b * 7 + f) * 262144 + nd;
        hr[f] = MAp[o] - MBp[o];
        hi[f] = MCp[o] + MDp[o];
    }
    const float CT[12] = {1.f, 0.8660254037844386f, 0.5f, 0.f, -0.5f, -0.8660254037844386f,
                          -1.f, -0.8660254037844386f, -0.5f, 0.f, 0.5f, 0.8660254037844386f};
    const float ST[12] = {0.f, 0.5f, 0.8660254037844386f, 1.f, 0.8660254037844386f, 0.5f,
                          0.f, -0.5f, -0.8660254037844386f, -1.f, -0.8660254037844386f, -0.5f};
    #pragma unroll
    for (int t = 0; t < 12; t++) {
        float acc = hr[0] + ((t & 1) ? -hr[6] : hr[6]);
        #pragma unroll
        for (int f = 1; f < 6; f++) {
            int k = (f * t) % 12;
            acc += 2.f * (hr[f] * CT[k] - hi[f] * ST[k]);
        }
        long long o = ((long long)b * 12 + t) * 262144 + nd;
        out[o] = x[o] + acc * (1.f / 12.f);
    }
}

// ---------------------------------------------------------------------------
extern "C" void kernel_launch(void* const* d_in, const int* in_sizes, int n_in,
                              void* d_out, int out_size)
{
    const float* x   = (const float*)d_in[0];
    const float* Wd1 = (const float*)d_in[1];  const float* bd1 = (const float*)d_in[2];
    const float* Wd2 = (const float*)d_in[3];  const float* bd2 = (const float*)d_in[4];
    const float* Wq  = (const float*)d_in[5];  const float* bq  = (const float*)d_in[6];
    const float* Wk  = (const float*)d_in[7];  const float* bk  = (const float*)d_in[8];
    const float* Wv  = (const float*)d_in[9];  const float* bv  = (const float*)d_in[10];
    const float* Wu1 = (const float*)d_in[11]; const float* bu1 = (const float*)d_in[12];
    const float* Wu2 = (const float*)d_in[13]; const float* bu2 = (const float*)d_in[14];
    const float* gamma = (const float*)d_in[15];
    const float* beta  = (const float*)d_in[16];
    const float* Wr1 = (const float*)d_in[17]; const float* br1 = (const float*)d_in[18];
    const float* Wr2 = (const float*)d_in[19]; const float* br2 = (const float*)d_in[20];
    const float* Wi1 = (const float*)d_in[21]; const float* bi1 = (const float*)d_in[22];
    const float* Wi2 = (const float*)d_in[23]; const float* bi2 = (const float*)d_in[24];
    float* out = (float*)d_out;

    float* arena = nullptr;
    cudaGetSymbolAddress((void**)&arena, g_arena);

    float* XT = arena + OFF_XT;   float* U  = XT;   // aliased (disjoint lifetimes)
    float* S  = arena + OFF_S;    float* ON = S;    // aliased
    float* H1 = arena + OFF_H1;
    float* Y  = arena + OFF_Y;
    float* Q  = arena + OFF_Q;
    float* Km = arena + OFF_K;
    float* V  = arena + OFF_V;
    float* O  = arena + OFF_O;
    float* HN = arena + OFF_HN;   float* GH = HN;   // aliased
    float* RE = arena + OFF_RE;
    float* IM = arena + OFF_IM;
    float* MA = arena + OFF_MA;
    float* MB = arena + OFF_MB;
    float* MC = arena + OFF_MC;
    float* MD = arena + OFF_MD;

    // ---- node branch ----
    transpose_xt<<<49152, 256>>>(x, XT);
    gemm_kernel<1, true><<<dim3(1, 256, 1), 256>>>(XT, Wd1, bd1, H1, 32768, 128, 1536, 1.f, 0, 0, 0);
    gemm_kernel<0, true><<<dim3(1, 256, 1), 256>>>(H1, Wd2, bd2, Y, 32768, 128, 128, 1.f, 0, 0, 0);
    gemm_kernel<0, true><<<dim3(1, 256, 1), 256>>>(Y, Wq, bq, Q, 32768, 128, 128, 1.f, 0, 0, 0);
    gemm_kernel<0, true><<<dim3(1, 256, 1), 256>>>(Y, Wk, bk, Km, 32768, 128, 128, 1.f, 0, 0, 0);
    gemm_kernel<0, true><<<dim3(1, 256, 1), 256>>>(Y, Wv, bv, V, 32768, 128, 128, 1.f, 0, 0, 0);

    // ---- attention ----
    gemm_kernel<0, true><<<dim3(16, 16, 16), 256>>>(Q, Km, nullptr, S, 2048, 2048, 128,
                                                    0.125f, 262144, 262144, 4194304);
    softmax2048<<<32768, 256>>>(S);
    gemm_kernel<0, false><<<dim3(1, 16, 16), 256>>>(S, V, nullptr, O, 2048, 128, 2048,
                                                    1.f, 4194304, 262144, 262144);

    // ---- conv_up ----
    gemm_kernel<1, true><<<dim3(12, 256, 1), 256>>>(O, Wu1, bu1, U, 32768, 1536, 128, 1.f, 0, 0, 0);
    gemm_kernel<0, true><<<dim3(12, 256, 1), 256>>>(U, Wu2, bu2, ON, 32768, 1536, 1536, 1.f, 0, 0, 0);

    // ---- residual + LN ----
    resid_ln<<<786432, 128>>>(ON, x, gamma, beta, HN);

    // ---- rfft (T=12 -> 7 bins) ----
    dft12<<<16384, 256>>>(HN, RE, IM);

    // ---- 4 MLP evaluations: MA=R(re), MB=I(im), MC=I(re), MD=R(im) ----
    gemm_kernel<2, true><<<dim3(1, 1792, 1), 256>>>(RE, Wr1, br1, GH, 229376, 128, 128, 1.f, 0, 0, 0);
    gemm_kernel<0, true><<<dim3(1, 1792, 1), 256>>>(GH, Wr2, br2, MA, 229376, 128, 128, 1.f, 0, 0, 0);
    gemm_kernel<2, true><<<dim3(1, 1792, 1), 256>>>(IM, Wi1, bi1, GH, 229376, 128, 128, 1.f, 0, 0, 0);
    gemm_kernel<0, true><<<dim3(1, 1792, 1), 256>>>(GH, Wi2, bi2, MB, 229376, 128, 128, 1.f, 0, 0, 0);
    gemm_kernel<2, true><<<dim3(1, 1792, 1), 256>>>(RE, Wi1, bi1, GH, 229376, 128, 128, 1.f, 0, 0, 0);
    gemm_kernel<0, true><<<dim3(1, 1792, 1), 256>>>(GH, Wi2, bi2, MC, 229376, 128, 128, 1.f, 0, 0, 0);
    gemm_kernel<2, true><<<dim3(1, 1792, 1), 256>>>(IM, Wr1, br1, GH, 229376, 128, 128, 1.f, 0, 0, 0);
    gemm_kernel<0, true><<<dim3(1, 1792, 1), 256>>>(GH, Wr2, br2, MD, 229376, 128, 128, 1.f, 0, 0, 0);

    // ---- irfft + residual ----
    irfft12<<<16384, 256>>>(MA, MB, MC, MD, x, out);
}

// round 2
// speedup vs baseline: 1.0003x; 1.0003x over previous
#include <cuda_runtime.h>
#include <math.h>

// ---------------------------------------------------------------------------
// Problem constants: B=16, T=12, N=2048, D=128
//   x: [16,12,2048,128] f32
// ---------------------------------------------------------------------------

#define BMT 128
#define BNT 128
#define BKT 8
#define TMT 8
#define TNT 8

// -------------------- scratch arena (float elements) -----------------------
// XT  [B,N,T*D] 50331648   (aliased by U  [32768,1536])
// S   [16,2048,2048] 67108864 (aliased by ON [32768,1536] = 50331648)
// H1,Y,Q,K,V,O: 4194304 each
// HN  [B,T,N,D] 50331648   (aliased by GH [229376,128] = 29360128)
// RE,IM,MA,MB,MC,MD: 29360128 each
static const long long OFF_XT = 0;
static const long long OFF_S  = 50331648LL;
static const long long OFF_H1 = 117440512LL;
static const long long OFF_Y  = 121634816LL;
static const long long OFF_Q  = 125829120LL;
static const long long OFF_K  = 130023424LL;
static const long long OFF_V  = 134217728LL;
static const long long OFF_O  = 138412032LL;
static const long long OFF_HN = 142606336LL;
static const long long OFF_RE = 192937984LL;
static const long long OFF_IM = 222298112LL;
static const long long OFF_MA = 251658240LL;
static const long long OFF_MB = 281018368LL;
static const long long OFF_MC = 310378496LL;
static const long long OFF_MD = 339738624LL;

__device__ float g_arena[369098752];   // ~1.48 GB scratch

// -------------------- epilogue ----------------------------------------------
template <int EPI>
__device__ __forceinline__ float epi_f(float v) {
    if (EPI == 1) return v > 0.f ? v : 0.f;                                   // relu
    if (EPI == 2) return 0.5f * v * (1.f + erff(v * 0.7071067811865476f));    // exact gelu
    return v;
}

// -------------------- SGEMM: C = epi(alpha * A@op(B) + bias) ----------------
// A: [M,K] row-major.  BT=true: B is [N,K] (C = A*B^T).  BT=false: B is [K,N].
// Batched via blockIdx.z with element strides sA/sB/sC.
// Requires: M%128==0, N%128==0, K%8==0.
template <int EPI, bool BT>
__global__ void __launch_bounds__(256)
gemm_kernel(const float* __restrict__ A, const float* __restrict__ B,
            const float* __restrict__ bias, float* __restrict__ C,
            int M, int N, int K, float alpha,
            long long sA, long long sB, long long sC)
{
    __shared__ __align__(16) float As[BKT][BMT];
    __shared__ __align__(16) float Bs[BKT][BNT];

    const int tid = threadIdx.x;
    const int bx = blockIdx.x, by = blockIdx.y, bz = blockIdx.z;

    const float* Ap = A + (long long)bz * sA + (long long)by * BMT * K;
    const float* Bp;
    if (BT) Bp = B + (long long)bz * sB + (long long)bx * BNT * K;
    else    Bp = B + (long long)bz * sB + bx * BNT;
    float* Cp = C + (long long)bz * sC + (long long)by * BMT * N + bx * BNT;

    const int aRow = tid >> 1, aCol = (tid & 1) << 2;   // 128 x 8 tile, float4
    const int bRowN = tid >> 5, bColN = (tid & 31) << 2; // [K,N] loader

    const int tr = (tid >> 4) << 3;  // 16x16 thread grid, 8x8 microtile
    const int tc = (tid & 15) << 3;

    float acc[TMT][TNT];
    #pragma unroll
    for (int i = 0; i < TMT; i++)
        #pragma unroll
        for (int j = 0; j < TNT; j++) acc[i][j] = 0.f;

    for (int k0 = 0; k0 < K; k0 += BKT) {
        float4 av = *(const float4*)(Ap + (long long)aRow * K + k0 + aCol);
        As[aCol + 0][aRow] = av.x;
        As[aCol + 1][aRow] = av.y;
        As[aCol + 2][aRow] = av.z;
        As[aCol + 3][aRow] = av.w;
        if (BT) {
            float4 bv = *(const float4*)(Bp + (long long)aRow * K + k0 + aCol);
            Bs[aCol + 0][aRow] = bv.x;
            Bs[aCol + 1][aRow] = bv.y;
            Bs[aCol + 2][aRow] = bv.z;
            Bs[aCol + 3][aRow] = bv.w;
        } else {
            float4 bv = *(const float4*)(Bp + (long long)(k0 + bRowN) * N + bColN);
            *(float4*)&Bs[bRowN][bColN] = bv;
        }
        __syncthreads();

        #pragma unroll
        for (int kk = 0; kk < BKT; kk++) {
            float a[TMT], b[TNT];
            *(float4*)&a[0] = *(const float4*)&As[kk][tr];
            *(float4*)&a[4] = *(const float4*)&As[kk][tr + 4];
            *(float4*)&b[0] = *(const float4*)&Bs[kk][tc];
            *(float4*)&b[4] = *(const float4*)&Bs[kk][tc + 4];
            #pragma unroll
            for (int i = 0; i < TMT; i++)
                #pragma unroll
                for (int j = 0; j < TNT; j++)
                    acc[i][j] = fmaf(a[i], b[j], acc[i][j]);
        }
        __syncthreads();
    }

    float bvv[TNT];
    #pragma unroll
    for (int j = 0; j < TNT; j++)
        bvv[j] = bias ? bias[bx * BNT + tc + j] : 0.f;

    #pragma unroll
    for (int i = 0; i < TMT; i++) {
        float tmp[TNT];
        #pragma unroll
        for (int j = 0; j < TNT; j++)
            tmp[j] = epi_f<EPI>(acc[i][j] * alpha + bvv[j]);
        *(float4*)(Cp + (long long)(tr + i) * N + tc)     = *(float4*)&tmp[0];
        *(float4*)(Cp + (long long)(tr + i) * N + tc + 4) = *(float4*)&tmp[4];
    }
}

// -------------------- x [B,T,N,D] -> xt [B,N,T*D] ---------------------------
__global__ void transpose_xt(const float* __restrict__ x, float* __restrict__ xt) {
    int gid = blockIdx.x * 256 + threadIdx.x;        // < 786432*32
    int r = gid >> 5;                                // row in [0, B*T*N)
    int c = (gid & 31) << 2;
    int b = r / (12 * 2048);
    int rem = r - b * (12 * 2048);
    int t = rem >> 11;
    int n = rem & 2047;
    float4 v = *(const float4*)(x + (long long)r * 128 + c);
    *(float4*)(xt + ((long long)(b * 2048 + n) * 1536 + t * 128 + c)) = v;
}

// -------------------- row softmax (row length 2048) -------------------------
__global__ void softmax2048(float* __restrict__ S) {
    float* row = S + (long long)blockIdx.x * 2048;
    int t = threadIdx.x;
    float v[8];
    float mx = -3.4e38f;
    #pragma unroll
    for (int i = 0; i < 8; i++) { v[i] = row[t + (i << 8)]; mx = fmaxf(mx, v[i]); }
    __shared__ float red[8];
    #pragma unroll
    for (int o = 16; o; o >>= 1) mx = fmaxf(mx, __shfl_xor_sync(0xffffffffu, mx, o));
    if ((t & 31) == 0) red[t >> 5] = mx;
    __syncthreads();
    mx = red[0];
    #pragma unroll
    for (int i = 1; i < 8; i++) mx = fmaxf(mx, red[i]);
    float s = 0.f;
    #pragma unroll
    for (int i = 0; i < 8; i++) { v[i] = __expf(v[i] - mx); s += v[i]; }
    #pragma unroll
    for (int o = 16; o; o >>= 1) s += __shfl_xor_sync(0xffffffffu, s, o);
    __syncthreads();
    if ((t & 31) == 0) red[t >> 5] = s;
    __syncthreads();
    s = 0.f;
    #pragma unroll
    for (int i = 0; i < 8; i++) s += red[i];
    float inv = 1.f / s;
    #pragma unroll
    for (int i = 0; i < 8; i++) row[t + (i << 8)] = v[i] * inv;
}

// -------------------- residual + LayerNorm ----------------------------------
// ON: [B,N,T*D] (conv_up output), x/HN: [B,T,N,D]. One row (128) per block.
__global__ void resid_ln(const float* __restrict__ ON, const float* __restrict__ x,
                         const float* __restrict__ gamma, const float* __restrict__ beta,
                         float* __restrict__ HN)
{
    long long r = blockIdx.x;                      // < B*T*N = 786432
    int d = threadIdx.x;
    int b = (int)(r / 24576);
    int rem = (int)(r % 24576);
    int t = rem >> 11;
    int n = rem & 2047;
    float v = ON[((long long)(b * 2048 + n)) * 1536 + t * 128 + d] + x[r * 128 + d];
    float s = v, q = v * v;
    #pragma unroll
    for (int o = 16; o; o >>= 1) {
        s += __shfl_xor_sync(0xffffffffu, s, o);
        q += __shfl_xor_sync(0xffffffffu, q, o);
    }
    __shared__ float ss[4], qq[4];
    int w = d >> 5, lane = d & 31;
    if (lane == 0) { ss[w] = s; qq[w] = q; }
    __syncthreads();
    s = ss[0] + ss[1] + ss[2] + ss[3];
    q = qq[0] + qq[1] + qq[2] + qq[3];
    float mean = s * (1.f / 128.f);
    float var = q * (1.f / 128.f) - mean * mean;
    float rstd = rsqrtf(var + 1e-5f);
    HN[r * 128 + d] = (v - mean) * rstd * gamma[d] + beta[d];
}

// -------------------- 12-point rfft over time axis --------------------------
__global__ void dft12(const float* __restrict__ hn,
                      float* __restrict__ re, float* __restrict__ im)
{
    int idx = blockIdx.x * 256 + threadIdx.x;      // < B*N*D = 4194304
    int b = idx >> 18;
    int nd = idx & 262143;
    const float* p = hn + (long long)b * 12 * 262144 + nd;
    float vt[12];
    #pragma unroll
    for (int t = 0; t < 12; t++) vt[t] = p[(long long)t * 262144];
    const float CT[12] = {1.f, 0.8660254037844386f, 0.5f, 0.f, -0.5f, -0.8660254037844386f,
                          -1.f, -0.8660254037844386f, -0.5f, 0.f, 0.5f, 0.8660254037844386f};
    const float ST[12] = {0.f, 0.5f, 0.8660254037844386f, 1.f, 0.8660254037844386f, 0.5f,
                          0.f, -0.5f, -0.8660254037844386f, -1.f, -0.8660254037844386f, -0.5f};
    #pragma unroll
    for (int f = 0; f < 7; f++) {
        float sr = 0.f, si = 0.f;
        #pragma unroll
        for (int t = 0; t < 12; t++) {
            int k = (f * t) % 12;
            sr += vt[t] * CT[k];
            si -= vt[t] * ST[k];
        }
        long long o = ((long long)b * 7 + f) * 262144 + nd;
        re[o] = sr;
        im[o] = si;
    }
}

// -------------------- irfft(n=12) + residual --------------------------------
// hr = MA - MB, hi = MC + MD. Imag parts of bins 0 and 6 are ignored (c2r).
__global__ void irfft12(const float* __restrict__ MAp, const float* __restrict__ MBp,
                        const float* __restrict__ MCp, const float* __restrict__ MDp,
                        const float* __restrict__ x, float* __restrict__ out)
{
    int idx = blockIdx.x * 256 + threadIdx.x;      // < 4194304
    int b = idx >> 18;
    int nd = idx & 262143;
    float hr[7], hi[7];
    #pragma unroll
    for (int f = 0; f < 7; f++) {
        long long o = ((long long)b * 7 + f) * 262144 + nd;
        hr[f] = MAp[o] - MBp[o];
        hi[f] = MCp[o] + MDp[o];
    }
    const float CT[12] = {1.f, 0.8660254037844386f, 0.5f, 0.f, -0.5f, -0.8660254037844386f,
                          -1.f, -0.8660254037844386f, -0.5f, 0.f, 0.5f, 0.8660254037844386f};
    const float ST[12] = {0.f, 0.5f, 0.8660254037844386f, 1.f, 0.8660254037844386f, 0.5f,
                          0.f, -0.5f, -0.8660254037844386f, -1.f, -0.8660254037844386f, -0.5f};
    #pragma unroll
    for (int t = 0; t < 12; t++) {
        float acc = hr[0] + ((t & 1) ? -hr[6] : hr[6]);
        #pragma unroll
        for (int f = 1; f < 6; f++) {
            int k = (f * t) % 12;
            acc += 2.f * (hr[f] * CT[k] - hi[f] * ST[k]);
        }
        long long o = ((long long)b * 12 + t) * 262144 + nd;
        out[o] = x[o] + acc * (1.f / 12.f);
    }
}

// ---------------------------------------------------------------------------
extern "C" void kernel_launch(void* const* d_in, const int* in_sizes, int n_in,
                              void* d_out, int out_size)
{
    const float* x   = (const float*)d_in[0];
    const float* Wd1 = (const float*)d_in[1];  const float* bd1 = (const float*)d_in[2];
    const float* Wd2 = (const float*)d_in[3];  const float* bd2 = (const float*)d_in[4];
    const float* Wq  = (const float*)d_in[5];  const float* bq  = (const float*)d_in[6];
    const float* Wk  = (const float*)d_in[7];  const float* bk  = (const float*)d_in[8];
    const float* Wv  = (const float*)d_in[9];  const float* bv  = (const float*)d_in[10];
    const float* Wu1 = (const float*)d_in[11]; const float* bu1 = (const float*)d_in[12];
    const float* Wu2 = (const float*)d_in[13]; const float* bu2 = (const float*)d_in[14];
    const float* gamma = (const float*)d_in[15];
    const float* beta  = (const float*)d_in[16];
    const float* Wr1 = (const float*)d_in[17]; const float* br1 = (const float*)d_in[18];
    const float* Wr2 = (const float*)d_in[19]; const float* br2 = (const float*)d_in[20];
    const float* Wi1 = (const float*)d_in[21]; const float* bi1 = (const float*)d_in[22];
    const float* Wi2 = (const float*)d_in[23]; const float* bi2 = (const float*)d_in[24];
    float* out = (float*)d_out;

    float* arena = nullptr;
    cudaGetSymbolAddress((void**)&arena, g_arena);

    float* XT = arena + OFF_XT;   float* U  = XT;   // aliased (disjoint lifetimes)
    float* S  = arena + OFF_S;    float* ON = S;    // aliased
    float* H1 = arena + OFF_H1;
    float* Y  = arena + OFF_Y;
    float* Q  = arena + OFF_Q;
    float* Km = arena + OFF_K;
    float* V  = arena + OFF_V;
    float* O  = arena + OFF_O;
    float* HN = arena + OFF_HN;   float* GH = HN;   // aliased
    float* RE = arena + OFF_RE;
    float* IM = arena + OFF_IM;
    float* MA = arena + OFF_MA;
    float* MB = arena + OFF_MB;
    float* MC = arena + OFF_MC;
    float* MD = arena + OFF_MD;

    // ---- node branch ----
    transpose_xt<<<49152, 256>>>(x, XT);
    gemm_kernel<1, true><<<dim3(1, 256, 1), 256>>>(XT, Wd1, bd1, H1, 32768, 128, 1536, 1.f, 0, 0, 0);
    gemm_kernel<0, true><<<dim3(1, 256, 1), 256>>>(H1, Wd2, bd2, Y, 32768, 128, 128, 1.f, 0, 0, 0);
    gemm_kernel<0, true><<<dim3(1, 256, 1), 256>>>(Y, Wq, bq, Q, 32768, 128, 128, 1.f, 0, 0, 0);
    gemm_kernel<0, true><<<dim3(1, 256, 1), 256>>>(Y, Wk, bk, Km, 32768, 128, 128, 1.f, 0, 0, 0);
    gemm_kernel<0, true><<<dim3(1, 256, 1), 256>>>(Y, Wv, bv, V, 32768, 128, 128, 1.f, 0, 0, 0);

    // ---- attention ----
    gemm_kernel<0, true><<<dim3(16, 16, 16), 256>>>(Q, Km, nullptr, S, 2048, 2048, 128,
                                                    0.125f, 262144, 262144, 4194304);
    softmax2048<<<32768, 256>>>(S);
    gemm_kernel<0, false><<<dim3(1, 16, 16), 256>>>(S, V, nullptr, O, 2048, 128, 2048,
                                                    1.f, 4194304, 262144, 262144);

    // ---- conv_up ----
    gemm_kernel<1, true><<<dim3(12, 256, 1), 256>>>(O, Wu1, bu1, U, 32768, 1536, 128, 1.f, 0, 0, 0);
    gemm_kernel<0, true><<<dim3(12, 256, 1), 256>>>(U, Wu2, bu2, ON, 32768, 1536, 1536, 1.f, 0, 0, 0);

    // ---- residual + LN ----
    resid_ln<<<786432, 128>>>(ON, x, gamma, beta, HN);

    // ---- rfft (T=12 -> 7 bins) ----
    dft12<<<16384, 256>>>(HN, RE, IM);

    // ---- 4 MLP evaluations: MA=R(re), MB=I(im), MC=I(re), MD=R(im) ----
    gemm_kernel<2, true><<<dim3(1, 1792, 1), 256>>>(RE, Wr1, br1, GH, 229376, 128, 128, 1.f, 0, 0, 0);
    gemm_kernel<0, true><<<dim3(1, 1792, 1), 256>>>(GH, Wr2, br2, MA, 229376, 128, 128, 1.f, 0, 0, 0);
    gemm_kernel<2, true><<<dim3(1, 1792, 1), 256>>>(IM, Wi1, bi1, GH, 229376, 128, 128, 1.f, 0, 0, 0);
    gemm_kernel<0, true><<<dim3(1, 1792, 1), 256>>>(GH, Wi2, bi2, MB, 229376, 128, 128, 1.f, 0, 0, 0);
    gemm_kernel<2, true><<<dim3(1, 1792, 1), 256>>>(RE, Wi1, bi1, GH, 229376, 128, 128, 1.f, 0, 0, 0);
    gemm_kernel<0, true><<<dim3(1, 1792, 1), 256>>>(GH, Wi2, bi2, MC, 229376, 128, 128, 1.f, 0, 0, 0);
    gemm_kernel<2, true><<<dim3(1, 1792, 1), 256>>>(IM, Wr1, br1, GH, 229376, 128, 128, 1.f, 0, 0, 0);
    gemm_kernel<0, true><<<dim3(1, 1792, 1), 256>>>(GH, Wr2, br2, MD, 229376, 128, 128, 1.f, 0, 0, 0);

    // ---- irfft + residual ----
    irfft12<<<16384, 256>>>(MA, MB, MC, MD, x, out);
}

// round 5
// speedup vs baseline: 1.8581x; 1.8576x over previous
#include <cuda_runtime.h>
#include <cuda_bf16.h>
#include <stdint.h>
#include <math.h>

// B=16, T=12, N=2048, D=128.  x: [16,12,2048,128] f32
static const long long OFF_XT = 0;            // 50331648 (alias U)
static const long long OFF_S  = 50331648LL;   // 67108864 (alias ON)
static const long long OFF_H1 = 117440512LL;
static const long long OFF_Y  = 121634816LL;
static const long long OFF_Q  = 125829120LL;
static const long long OFF_K  = 130023424LL;
static const long long OFF_V  = 134217728LL;
static const long long OFF_VT = 138412032LL;
static const long long OFF_O  = 142606336LL;
static const long long OFF_HN = 146800640LL;  // 50331648
static const long long OFF_RE = 197132288LL;  // 29360128 (alias HR)
static const long long OFF_IM = 226492416LL;  // 29360128 (alias HI)
static const long long OFF_HRC= 255852544LL;  // 58720256
static const long long OFF_HIC= 314572800LL;  // 58720256
static const long long OFF_WCR= 373293056LL;
static const long long OFF_WCI= 373325824LL;
static const long long OFF_BCR= 373358592LL;
static const long long OFF_BCI= 373358720LL;

__device__ float g_arena[373358848];

__device__ __forceinline__ float epi_f(float v, int epi) {
    if (epi == 1) return v > 0.f ? v : 0.f;
    if (epi == 2) return 0.5f * v * (1.f + erff(v * 0.7071067811865476f));
    return v;
}

__device__ __forceinline__ void ldsm4(uint32_t &r0, uint32_t &r1, uint32_t &r2, uint32_t &r3,
                                      uint32_t addr) {
    asm volatile("ldmatrix.sync.aligned.m8n8.x4.shared.b16 {%0,%1,%2,%3}, [%4];"
                 : "=r"(r0), "=r"(r1), "=r"(r2), "=r"(r3) : "r"(addr));
}
__device__ __forceinline__ void mma_bf16(float* d, const uint32_t* a, const uint32_t* b) {
    asm volatile("mma.sync.aligned.m16n8k16.row.col.f32.bf16.bf16.f32 "
                 "{%0,%1,%2,%3}, {%4,%5,%6,%7}, {%8,%9}, {%0,%1,%2,%3};"
                 : "+f"(d[0]), "+f"(d[1]), "+f"(d[2]), "+f"(d[3])
                 : "r"(a[0]), "r"(a[1]), "r"(a[2]), "r"(a[3]), "r"(b[0]), "r"(b[1]));
}

__device__ __forceinline__ void split_pack(float4 v0, float4 v1, uint4 &hi, uint4 &lo) {
    float f[8] = {v0.x, v0.y, v0.z, v0.w, v1.x, v1.y, v1.z, v1.w};
    uint32_t h[4], l[4];
#pragma unroll
    for (int i = 0; i < 4; i++) {
        __nv_bfloat16 h0 = __float2bfloat16_rn(f[2*i]);
        __nv_bfloat16 h1 = __float2bfloat16_rn(f[2*i+1]);
        __nv_bfloat16 l0 = __float2bfloat16_rn(f[2*i]   - __bfloat162float(h0));
        __nv_bfloat16 l1 = __float2bfloat16_rn(f[2*i+1] - __bfloat162float(h1));
        h[i] = ((uint32_t)__bfloat16_as_ushort(h1) << 16) | (uint32_t)__bfloat16_as_ushort(h0);
        l[i] = ((uint32_t)__bfloat16_as_ushort(l1) << 16) | (uint32_t)__bfloat16_as_ushort(l0);
    }
    hi = make_uint4(h[0], h[1], h[2], h[3]);
    lo = make_uint4(l[0], l[1], l[2], l[3]);
}

// C[M,N](ld=ldc) = epi(alpha * A[M,K] @ B[N,K]^T + bias). batch via blockIdx.z.
// grid.y = M/128, grid.x = N/128, K % 32 == 0. 256 threads, 32KB static smem.
__global__ void __launch_bounds__(256)
gemm_bf16x3(const float* __restrict__ A, const float* __restrict__ B,
            const float* __restrict__ bias, float* __restrict__ C,
            int K, int ldc, float alpha, int epi,
            long long sA, long long sB, long long sC)
{
    __shared__ __align__(16) uint4 sm[2048];   // A:[0,1024) B:[1024,2048) uint4
    const int t = threadIdx.x;
    const int bx = blockIdx.x, by = blockIdx.y, bz = blockIdx.z;
    const int lane = t & 31;

    const int lr = t >> 2, lc = t & 3, s7 = lr & 7;
    const float* Ag0 = A + (long long)bz * sA + (long long)(by * 128 + lr) * K + lc * 8;
    const float* Ag1 = Ag0 + (long long)64 * K;
    const float* Bg0 = B + (long long)bz * sB + (long long)(bx * 128 + lr) * K + lc * 8;
    const float* Bg1 = Bg0 + (long long)64 * K;

    const int sub = lane >> 3, l7 = lane & 7;
    const int wm = (t >> 7) * 64, wn = ((t >> 5) & 3) * 32;
    const int aRowOff = wm + l7 + ((sub & 1) << 3);
    const int aSel = sub >> 1;
    const int bRowOff = wn + l7 + ((sub >> 1) << 3);
    const int bSel = sub & 1;
    const uint32_t smemBase = (uint32_t)__cvta_generic_to_shared(sm);

    uint4* bA0 = sm + lr * 8;        uint4* bA1 = bA0 + 512;
    uint4* bB0 = sm + 1024 + lr * 8; uint4* bB1 = bB0 + 512;

    float acc[4][4][4];
#pragma unroll
    for (int i = 0; i < 4; i++)
#pragma unroll
        for (int j = 0; j < 4; j++)
#pragma unroll
            for (int q = 0; q < 4; q++) acc[i][j][q] = 0.f;

    const int nk = K >> 5;
    {   // tile 0 -> smem
        uint4 hi, lo;
        split_pack(*(const float4*)Ag0, *(const float4*)(Ag0+4), hi, lo);
        bA0[lc ^ s7] = hi; bA0[(lc+4) ^ s7] = lo;
        split_pack(*(const float4*)Ag1, *(const float4*)(Ag1+4), hi, lo);
        bA1[lc ^ s7] = hi; bA1[(lc+4) ^ s7] = lo;
        split_pack(*(const float4*)Bg0, *(const float4*)(Bg0+4), hi, lo);
        bB0[lc ^ s7] = hi; bB0[(lc+4) ^ s7] = lo;
        split_pack(*(const float4*)Bg1, *(const float4*)(Bg1+4), hi, lo);
        bB1[lc ^ s7] = hi; bB1[(lc+4) ^ s7] = lo;
    }
    __syncthreads();

    for (int s = 0; s < nk; s++) {
        float4 a00, a01, a10, a11, b00, b01, b10, b11;
        const bool more = (s + 1) < nk;
        if (more) {   // prefetch next K-tile into registers
            const float* pa0 = Ag0 + (s+1)*32; const float* pa1 = Ag1 + (s+1)*32;
            const float* pb0 = Bg0 + (s+1)*32; const float* pb1 = Bg1 + (s+1)*32;
            a00 = *(const float4*)pa0; a01 = *(const float4*)(pa0+4);
            a10 = *(const float4*)pa1; a11 = *(const float4*)(pa1+4);
            b00 = *(const float4*)pb0; b01 = *(const float4*)(pb0+4);
            b10 = *(const float4*)pb1; b11 = *(const float4*)(pb1+4);
        }
#pragma unroll
        for (int kh = 0; kh < 2; kh++) {
            uint32_t ah[4][4], al[4][4], bh[4][2], bl[4][2];
#pragma unroll
            for (int mf = 0; mf < 4; mf++) {
                const uint32_t rb = smemBase + (uint32_t)(aRowOff + mf * 16) * 128;
                const int u0 = 2 * kh + aSel;
                ldsm4(ah[mf][0], ah[mf][1], ah[mf][2], ah[mf][3], rb + ((u0 ^ l7) << 4));
                ldsm4(al[mf][0], al[mf][1], al[mf][2], al[mf][3], rb + (((u0 + 4) ^ l7) << 4));
            }
#pragma unroll
            for (int np = 0; np < 2; np++) {
                const uint32_t rb = smemBase + 16384 + (uint32_t)(bRowOff + np * 16) * 128;
                const int u0 = 2 * kh + bSel;
                uint32_t r0, r1, r2, r3;
                ldsm4(r0, r1, r2, r3, rb + ((u0 ^ l7) << 4));
                bh[np*2][0] = r0; bh[np*2][1] = r1; bh[np*2+1][0] = r2; bh[np*2+1][1] = r3;
                ldsm4(r0, r1, r2, r3, rb + (((u0 + 4) ^ l7) << 4));
                bl[np*2][0] = r0; bl[np*2][1] = r1; bl[np*2+1][0] = r2; bl[np*2+1][1] = r3;
            }
#pragma unroll
            for (int mf = 0; mf < 4; mf++)
#pragma unroll
                for (int nf = 0; nf < 4; nf++) {
                    mma_bf16(acc[mf][nf], ah[mf], bh[nf]);
                    mma_bf16(acc[mf][nf], ah[mf], bl[nf]);
                    mma_bf16(acc[mf][nf], al[mf], bh[nf]);
                }
        }
        if (more) {
            __syncthreads();   // all reads of smem done
            uint4 hi, lo;
            split_pack(a00, a01, hi, lo); bA0[lc ^ s7] = hi; bA0[(lc+4) ^ s7] = lo;
            split_pack(a10, a11, hi, lo); bA1[lc ^ s7] = hi; bA1[(lc+4) ^ s7] = lo;
            split_pack(b00, b01, hi, lo); bB0[lc ^ s7] = hi; bB0[(lc+4) ^ s7] = lo;
            split_pack(b10, b11, hi, lo); bB1[lc ^ s7] = hi; bB1[(lc+4) ^ s7] = lo;
            __syncthreads();
        }
    }

    const int g = lane >> 2, tt = lane & 3;
    const long long rowBase = (long long)by * 128 + wm + g;
#pragma unroll
    for (int mf = 0; mf < 4; mf++) {
#pragma unroll
        for (int nf = 0; nf < 4; nf++) {
            const int col = bx * 128 + wn + nf * 8 + 2 * tt;
            float2 bv = make_float2(0.f, 0.f);
            if (bias) bv = *(const float2*)(bias + col);
            float* c0 = C + (long long)bz * sC + (rowBase + mf * 16) * ldc + col;
            float2 v;
            v.x = epi_f(acc[mf][nf][0] * alpha + bv.x, epi);
            v.y = epi_f(acc[mf][nf][1] * alpha + bv.y, epi);
            *(float2*)c0 = v;
            v.x = epi_f(acc[mf][nf][2] * alpha + bv.x, epi);
            v.y = epi_f(acc[mf][nf][3] * alpha + bv.y, epi);
            *(float2*)(c0 + 8LL * ldc) = v;
        }
    }
}

__global__ void transpose_xt(const float* __restrict__ x, float* __restrict__ xt) {
    int gid = blockIdx.x * 256 + threadIdx.x;
    int r = gid >> 5, c = (gid & 31) << 2;
    int b = r / 24576, rem = r - b * 24576, t = rem >> 11, n = rem & 2047;
    float4 v = *(const float4*)(x + (long long)r * 128 + c);
    *(float4*)(xt + ((long long)(b * 2048 + n) * 1536 + t * 128 + c)) = v;
}

__global__ void transpose_v(const float* __restrict__ V, float* __restrict__ VT) {
    __shared__ float tile[32][33];
    int b = blockIdx.z, n0 = blockIdx.x * 32, d0 = blockIdx.y * 32;
    const float* Vb = V + (long long)b * 262144;
    float* VTb = VT + (long long)b * 262144;
    int tx = threadIdx.x & 31, ty = threadIdx.x >> 5;
#pragma unroll
    for (int i = 0; i < 32; i += 8)
        tile[ty + i][tx] = Vb[(long long)(n0 + ty + i) * 128 + d0 + tx];
    __syncthreads();
#pragma unroll
    for (int i = 0; i < 32; i += 8)
        VTb[(long long)(d0 + ty + i) * 2048 + n0 + tx] = tile[tx][ty + i];
}

__global__ void softmax2048(float* __restrict__ S) {
    float* row = S + (long long)blockIdx.x * 2048;
    int t = threadIdx.x;
    float v[8], mx = -3.4e38f;
#pragma unroll
    for (int i = 0; i < 8; i++) { v[i] = row[t + (i << 8)]; mx = fmaxf(mx, v[i]); }
    __shared__ float red[8];
#pragma unroll
    for (int o = 16; o; o >>= 1) mx = fmaxf(mx, __shfl_xor_sync(0xffffffffu, mx, o));
    if ((t & 31) == 0) red[t >> 5] = mx;
    __syncthreads();
    mx = red[0];
#pragma unroll
    for (int i = 1; i < 8; i++) mx = fmaxf(mx, red[i]);
    float s = 0.f;
#pragma unroll
    for (int i = 0; i < 8; i++) { v[i] = __expf(v[i] - mx); s += v[i]; }
#pragma unroll
    for (int o = 16; o; o >>= 1) s += __shfl_xor_sync(0xffffffffu, s, o);
    __syncthreads();
    if ((t & 31) == 0) red[t >> 5] = s;
    __syncthreads();
    s = 0.f;
#pragma unroll
    for (int i = 0; i < 8; i++) s += red[i];
    float inv = 1.f / s;
#pragma unroll
    for (int i = 0; i < 8; i++) row[t + (i << 8)] = v[i] * inv;
}

__global__ void resid_ln(const float* __restrict__ ON, const float* __restrict__ x,
                         const float* __restrict__ gamma, const float* __restrict__ beta,
                         float* __restrict__ HN)
{
    long long r = blockIdx.x;
    int d = threadIdx.x;
    int b = (int)(r / 24576), rem = (int)(r % 24576), t = rem >> 11, n = rem & 2047;
    float v = ON[((long long)(b * 2048 + n)) * 1536 + t * 128 + d] + x[r * 128 + d];
    float s = v, q = v * v;
#pragma unroll
    for (int o = 16; o; o >>= 1) {
        s += __shfl_xor_sync(0xffffffffu, s, o);
        q += __shfl_xor_sync(0xffffffffu, q, o);
    }
    __shared__ float ss[4], qq[4];
    int w = d >> 5, lane = d & 31;
    if (lane == 0) { ss[w] = s; qq[w] = q; }
    __syncthreads();
    s = ss[0] + ss[1] + ss[2] + ss[3];
    q = qq[0] + qq[1] + qq[2] + qq[3];
    float mean = s * (1.f / 128.f);
    float var = q * (1.f / 128.f) - mean * mean;
    float rstd = rsqrtf(var + 1e-5f);
    HN[r * 128 + d] = (v - mean) * rstd * gamma[d] + beta[d];
}

__global__ void dft12(const float* __restrict__ hn,
                      float* __restrict__ re, float* __restrict__ im)
{
    int idx = blockIdx.x * 256 + threadIdx.x;
    int b = idx >> 18, nd = idx & 262143;
    const float* p = hn + (long long)b * 12 * 262144 + nd;
    float vt[12];
#pragma unroll
    for (int t = 0; t < 12; t++) vt[t] = p[(long long)t * 262144];
    const float CT[12] = {1.f, 0.8660254037844386f, 0.5f, 0.f, -0.5f, -0.8660254037844386f,
                          -1.f, -0.8660254037844386f, -0.5f, 0.f, 0.5f, 0.8660254037844386f};
    const float ST[12] = {0.f, 0.5f, 0.8660254037844386f, 1.f, 0.8660254037844386f, 0.5f,
                          0.f, -0.5f, -0.8660254037844386f, -1.f, -0.8660254037844386f, -0.5f};
#pragma unroll
    for (int f = 0; f < 7; f++) {
        float sr = 0.f, si = 0.f;
#pragma unroll
        for (int t = 0; t < 12; t++) {
            int k = (f * t) % 12;
            sr += vt[t] * CT[k];
            si -= vt[t] * ST[k];
        }
        long long o = ((long long)b * 7 + f) * 262144 + nd;
        re[o] = sr; im[o] = si;
    }
}

__global__ void build_wcat(const float* __restrict__ Wr2, const float* __restrict__ br2,
                           const float* __restrict__ Wi2, const float* __restrict__ bi2,
                           float* __restrict__ Wc_r, float* __restrict__ bc_r,
                           float* __restrict__ Wc_i, float* __restrict__ bc_i)
{
    int i = blockIdx.x * 256 + threadIdx.x;
    int n = i >> 8, k = i & 255;
    float vr, vi;
    if (k < 128) { vr = Wr2[n * 128 + k];        vi = Wi2[n * 128 + k]; }
    else         { vr = -Wi2[n * 128 + k - 128]; vi = Wr2[n * 128 + k - 128]; }
    Wc_r[i] = vr; Wc_i[i] = vi;
    if (i < 128) { bc_r[i] = br2[i] - bi2[i]; bc_i[i] = bi2[i] + br2[i]; }
}

__global__ void irfft12(const float* __restrict__ HR, const float* __restrict__ HI,
                        const float* __restrict__ x, float* __restrict__ out)
{
    int idx = blockIdx.x * 256 + threadIdx.x;
    int b = idx >> 18, nd = idx & 262143;
    float hr[7], hi[7];
#pragma unroll
    for (int f = 0; f < 7; f++) {
        long long o = ((long long)b * 7 + f) * 262144 + nd;
        hr[f] = HR[o]; hi[f] = HI[o];
    }
    const float CT[12] = {1.f, 0.8660254037844386f, 0.5f, 0.f, -0.5f, -0.8660254037844386f,
                          -1.f, -0.8660254037844386f, -0.5f, 0.f, 0.5f, 0.8660254037844386f};
    const float ST[12] = {0.f, 0.5f, 0.8660254037844386f, 1.f, 0.8660254037844386f, 0.5f,
                          0.f, -0.5f, -0.8660254037844386f, -1.f, -0.8660254037844386f, -0.5f};
#pragma unroll
    for (int t = 0; t < 12; t++) {
        float acc = hr[0] + ((t & 1) ? -hr[6] : hr[6]);
#pragma unroll
        for (int f = 1; f < 6; f++) {
            int k = (f * t) % 12;
            acc += 2.f * (hr[f] * CT[k] - hi[f] * ST[k]);
        }
        long long o = ((long long)b * 12 + t) * 262144 + nd;
        out[o] = x[o] + acc * (1.f / 12.f);
    }
}

extern "C" void kernel_launch(void* const* d_in, const int* in_sizes, int n_in,
                              void* d_out, int out_size)
{
    const float* x   = (const float*)d_in[0];
    const float* Wd1 = (const float*)d_in[1];  const float* bd1 = (const float*)d_in[2];
    const float* Wd2 = (const float*)d_in[3];  const float* bd2 = (const float*)d_in[4];
    const float* Wq  = (const float*)d_in[5];  const float* bq  = (const float*)d_in[6];
    const float* Wk  = (const float*)d_in[7];  const float* bk  = (const float*)d_in[8];
    const float* Wv  = (const float*)d_in[9];  const float* bv  = (const float*)d_in[10];
    const float* Wu1 = (const float*)d_in[11]; const float* bu1 = (const float*)d_in[12];
    const float* Wu2 = (const float*)d_in[13]; const float* bu2 = (const float*)d_in[14];
    const float* gamma = (const float*)d_in[15];
    const float* beta  = (const float*)d_in[16];
    const float* Wr1 = (const float*)d_in[17]; const float* br1 = (const float*)d_in[18];
    const float* Wr2 = (const float*)d_in[19]; const float* br2 = (const float*)d_in[20];
    const float* Wi1 = (const float*)d_in[21]; const float* bi1 = (const float*)d_in[22];
    const float* Wi2 = (const float*)d_in[23]; const float* bi2 = (const float*)d_in[24];
    float* out = (float*)d_out;

    float* arena = nullptr;
    cudaGetSymbolAddress((void**)&arena, g_arena);

    float* XT = arena + OFF_XT;   float* U  = XT;
    float* S  = arena + OFF_S;    float* ON = S;
    float* H1 = arena + OFF_H1;
    float* Y  = arena + OFF_Y;
    float* Q  = arena + OFF_Q;
    float* Km = arena + OFF_K;
    float* V  = arena + OFF_V;
    float* VT = arena + OFF_VT;
    float* O  = arena + OFF_O;
    float* HN = arena + OFF_HN;
    float* RE = arena + OFF_RE;   float* HR = RE;
    float* IM = arena + OFF_IM;   float* HI = IM;
    float* Hrc = arena + OFF_HRC;
    float* Hic = arena + OFF_HIC;
    float* WCR = arena + OFF_WCR; float* WCI = arena + OFF_WCI;
    float* BCR = arena + OFF_BCR; float* BCI = arena + OFF_BCI;

    // ---- node branch ----
    transpose_xt<<<49152, 256>>>(x, XT);
    gemm_bf16x3<<<dim3(1, 256, 1), 256>>>(XT, Wd1, bd1, H1, 1536, 128, 1.f, 1, 0, 0, 0);
    gemm_bf16x3<<<dim3(1, 256, 1), 256>>>(H1, Wd2, bd2, Y, 128, 128, 1.f, 0, 0, 0, 0);
    gemm_bf16x3<<<dim3(1, 256, 1), 256>>>(Y, Wq, bq, Q, 128, 128, 1.f, 0, 0, 0, 0);
    gemm_bf16x3<<<dim3(1, 256, 1), 256>>>(Y, Wk, bk, Km, 128, 128, 1.f, 0, 0, 0, 0);
    gemm_bf16x3<<<dim3(1, 256, 1), 256>>>(Y, Wv, bv, V, 128, 128, 1.f, 0, 0, 0, 0);

    // ---- attention ----
    gemm_bf16x3<<<dim3(16, 16, 16), 256>>>(Q, Km, nullptr, S, 128, 2048, 0.125f, 0,
                                           262144, 262144, 4194304);
    softmax2048<<<32768, 256>>>(S);
    transpose_v<<<dim3(64, 4, 16), 256>>>(V, VT);
    gemm_bf16x3<<<dim3(1, 16, 16), 256>>>(S, VT, nullptr, O, 2048, 128, 1.f, 0,
                                          4194304, 262144, 262144);

    // ---- conv_up ----
    gemm_bf16x3<<<dim3(12, 256, 1), 256>>>(O, Wu1, bu1, U, 128, 1536, 1.f, 1, 0, 0, 0);
    gemm_bf16x3<<<dim3(12, 256, 1), 256>>>(U, Wu2, bu2, ON, 1536, 1536, 1.f, 0, 0, 0, 0);

    // ---- residual + LN, rfft ----
    resid_ln<<<786432, 128>>>(ON, x, gamma, beta, HN);
    dft12<<<16384, 256>>>(HN, RE, IM);
    build_wcat<<<128, 256>>>(Wr2, br2, Wi2, bi2, WCR, BCR, WCI, BCI);

    // ---- fused FFT dual-path MLP ----
    gemm_bf16x3<<<dim3(1, 1792, 1), 256>>>(RE, Wr1, br1, Hrc,       128, 256, 1.f, 2, 0, 0, 0);
    gemm_bf16x3<<<dim3(1, 1792, 1), 256>>>(IM, Wi1, bi1, Hrc + 128, 128, 256, 1.f, 2, 0, 0, 0);
    gemm_bf16x3<<<dim3(1, 1792, 1), 256>>>(RE, Wi1, bi1, Hic,       128, 256, 1.f, 2, 0, 0, 0);
    gemm_bf16x3<<<dim3(1, 1792, 1), 256>>>(IM, Wr1, br1, Hic + 128, 128, 256, 1.f, 2, 0, 0, 0);
    gemm_bf16x3<<<dim3(1, 1792, 1), 256>>>(Hrc, WCR, BCR, HR, 256, 128, 1.f, 0, 0, 0, 0);
    gemm_bf16x3<<<dim3(1, 1792, 1), 256>>>(Hic, WCI, BCI, HI, 256, 128, 1.f, 0, 0, 0, 0);

    // ---- irfft + residual ----
    irfft12<<<16384, 256>>>(HR, HI, x, out);
}

// round 8
// speedup vs baseline: 1.8801x; 1.0118x over previous
#include <cuda_runtime.h>
#include <cuda_bf16.h>
#include <stdint.h>
#include <math.h>

// B=16, T=12, N=2048, D=128.  x: [16,12,2048,128] f32
static const long long OFF_XT = 0;            // 50331648 (alias U)
static const long long OFF_S  = 50331648LL;   // 67108864 (alias ON)
static const long long OFF_H1 = 117440512LL;
static const long long OFF_Y  = 121634816LL;
static const long long OFF_Q  = 125829120LL;
static const long long OFF_K  = 130023424LL;
static const long long OFF_V  = 134217728LL;
static const long long OFF_VT = 138412032LL;
static const long long OFF_O  = 142606336LL;
static const long long OFF_HN = 146800640LL;  // 50331648
static const long long OFF_RE = 197132288LL;  // 29360128 (alias HR)
static const long long OFF_IM = 226492416LL;  // 29360128 (alias HI)
static const long long OFF_HRC= 255852544LL;  // 58720256
static const long long OFF_HIC= 314572800LL;  // 58720256
static const long long OFF_WCR= 373293056LL;
static const long long OFF_WCI= 373325824LL;
static const long long OFF_BCR= 373358592LL;
static const long long OFF_BCI= 373358720LL;

__device__ float g_arena[373358848];

__device__ __forceinline__ float epi_f(float v, int epi) {
    if (epi == 1) return v > 0.f ? v : 0.f;
    if (epi == 2) return 0.5f * v * (1.f + erff(v * 0.7071067811865476f));
    return v;
}

__device__ __forceinline__ void ldsm4(uint32_t &r0, uint32_t &r1, uint32_t &r2, uint32_t &r3,
                                      uint32_t addr) {
    asm volatile("ldmatrix.sync.aligned.m8n8.x4.shared.b16 {%0,%1,%2,%3}, [%4];"
                 : "=r"(r0), "=r"(r1), "=r"(r2), "=r"(r3) : "r"(addr));
}
__device__ __forceinline__ void mma_bf16(float* d, const uint32_t* a, const uint32_t* b) {
    asm volatile("mma.sync.aligned.m16n8k16.row.col.f32.bf16.bf16.f32 "
                 "{%0,%1,%2,%3}, {%4,%5,%6,%7}, {%8,%9}, {%0,%1,%2,%3};"
                 : "+f"(d[0]), "+f"(d[1]), "+f"(d[2]), "+f"(d[3])
                 : "r"(a[0]), "r"(a[1]), "r"(a[2]), "r"(a[3]), "r"(b[0]), "r"(b[1]));
}

__device__ __forceinline__ void split_pack(float4 v0, float4 v1, uint4 &hi, uint4 &lo) {
    float f[8] = {v0.x, v0.y, v0.z, v0.w, v1.x, v1.y, v1.z, v1.w};
    uint32_t h[4], l[4];
#pragma unroll
    for (int i = 0; i < 4; i++) {
        __nv_bfloat16 h0 = __float2bfloat16_rn(f[2*i]);
        __nv_bfloat16 h1 = __float2bfloat16_rn(f[2*i+1]);
        __nv_bfloat16 l0 = __float2bfloat16_rn(f[2*i]   - __bfloat162float(h0));
        __nv_bfloat16 l1 = __float2bfloat16_rn(f[2*i+1] - __bfloat162float(h1));
        h[i] = ((uint32_t)__bfloat16_as_ushort(h1) << 16) | (uint32_t)__bfloat16_as_ushort(h0);
        l[i] = ((uint32_t)__bfloat16_as_ushort(l1) << 16) | (uint32_t)__bfloat16_as_ushort(l0);
    }
    hi = make_uint4(h[0], h[1], h[2], h[3]);
    lo = make_uint4(l[0], l[1], l[2], l[3]);
}

// C[M,N](ld=ldc) = epi(alpha * A[M,K] @ B[N,K]^T + bias). batch via blockIdx.z.
// grid.y = M/128, grid.x = N/128, K % 32 == 0. 256 threads, 64KB dynamic smem,
// double-buffered (2 x 32KB stages).
__global__ void __launch_bounds__(256)
gemm_bf16x3(const float* __restrict__ A, const float* __restrict__ B,
            const float* __restrict__ bias, float* __restrict__ C,
            int K, int ldc, float alpha, int epi,
            long long sA, long long sB, long long sC)
{
    extern __shared__ __align__(16) uint4 sm[];   // [2][A:1024|B:1024] uint4
    const int t = threadIdx.x;
    const int bx = blockIdx.x, by = blockIdx.y, bz = blockIdx.z;
    const int lane = t & 31;

    const int lr = t >> 2, lc = t & 3, s7 = lr & 7;
    const float* Ag0 = A + (long long)bz * sA + (long long)(by * 128 + lr) * K + lc * 8;
    const float* Ag1 = Ag0 + (long long)64 * K;
    const float* Bg0 = B + (long long)bz * sB + (long long)(bx * 128 + lr) * K + lc * 8;
    const float* Bg1 = Bg0 + (long long)64 * K;

    const int sub = lane >> 3, l7 = lane & 7;
    const int wm = (t >> 7) * 64, wn = ((t >> 5) & 3) * 32;
    const int aRowOff = wm + l7 + ((sub & 1) << 3);
    const int aSel = sub >> 1;
    const int bRowOff = wn + l7 + ((sub >> 1) << 3);
    const int bSel = sub & 1;
    const uint32_t smemBase = (uint32_t)__cvta_generic_to_shared(sm);

    float acc[4][4][4];
#pragma unroll
    for (int i = 0; i < 4; i++)
#pragma unroll
        for (int j = 0; j < 4; j++)
#pragma unroll
            for (int q = 0; q < 4; q++) acc[i][j][q] = 0.f;

    const int nk = K >> 5;
    {   // tile 0 -> buffer 0
        uint4 hi, lo;
        uint4* bA0 = sm + lr * 8;        uint4* bA1 = bA0 + 512;
        uint4* bB0 = sm + 1024 + lr * 8; uint4* bB1 = bB0 + 512;
        split_pack(*(const float4*)Ag0, *(const float4*)(Ag0+4), hi, lo);
        bA0[lc ^ s7] = hi; bA0[(lc+4) ^ s7] = lo;
        split_pack(*(const float4*)Ag1, *(const float4*)(Ag1+4), hi, lo);
        bA1[lc ^ s7] = hi; bA1[(lc+4) ^ s7] = lo;
        split_pack(*(const float4*)Bg0, *(const float4*)(Bg0+4), hi, lo);
        bB0[lc ^ s7] = hi; bB0[(lc+4) ^ s7] = lo;
        split_pack(*(const float4*)Bg1, *(const float4*)(Bg1+4), hi, lo);
        bB1[lc ^ s7] = hi; bB1[(lc+4) ^ s7] = lo;
    }
    __syncthreads();

    for (int s = 0; s < nk; s++) {
        float4 a00, a01, a10, a11, b00, b01, b10, b11;
        const bool more = (s + 1) < nk;
        if (more) {   // issue next K-tile loads early (overlap with MMA below)
            const float* pa0 = Ag0 + (s+1)*32; const float* pa1 = Ag1 + (s+1)*32;
            const float* pb0 = Bg0 + (s+1)*32; const float* pb1 = Bg1 + (s+1)*32;
            a00 = *(const float4*)pa0; a01 = *(const float4*)(pa0+4);
            a10 = *(const float4*)pa1; a11 = *(const float4*)(pa1+4);
            b00 = *(const float4*)pb0; b01 = *(const float4*)(pb0+4);
            b10 = *(const float4*)pb1; b11 = *(const float4*)(pb1+4);
        }
        const uint32_t stg = smemBase + (uint32_t)(s & 1) * 32768u;
#pragma unroll
        for (int kh = 0; kh < 2; kh++) {
            uint32_t ah[4][4], al[4][4], bh[4][2], bl[4][2];
#pragma unroll
            for (int mf = 0; mf < 4; mf++) {
                const uint32_t rb = stg + (uint32_t)(aRowOff + mf * 16) * 128;
                const int u0 = 2 * kh + aSel;
                ldsm4(ah[mf][0], ah[mf][1], ah[mf][2], ah[mf][3], rb + ((u0 ^ l7) << 4));
                ldsm4(al[mf][0], al[mf][1], al[mf][2], al[mf][3], rb + (((u0 + 4) ^ l7) << 4));
            }
#pragma unroll
            for (int np = 0; np < 2; np++) {
                const uint32_t rb = stg + 16384 + (uint32_t)(bRowOff + np * 16) * 128;
                const int u0 = 2 * kh + bSel;
                uint32_t r0, r1, r2, r3;
                ldsm4(r0, r1, r2, r3, rb + ((u0 ^ l7) << 4));
                bh[np*2][0] = r0; bh[np*2][1] = r1; bh[np*2+1][0] = r2; bh[np*2+1][1] = r3;
                ldsm4(r0, r1, r2, r3, rb + (((u0 + 4) ^ l7) << 4));
                bl[np*2][0] = r0; bl[np*2][1] = r1; bl[np*2+1][0] = r2; bl[np*2+1][1] = r3;
            }
#pragma unroll
            for (int mf = 0; mf < 4; mf++)
#pragma unroll
                for (int nf = 0; nf < 4; nf++) {
                    mma_bf16(acc[mf][nf], ah[mf], bh[nf]);
                    mma_bf16(acc[mf][nf], ah[mf], bl[nf]);
                    mma_bf16(acc[mf][nf], al[mf], bh[nf]);
                }
        }
        if (more) {   // store next tile into the other buffer (no barrier needed first)
            const uint32_t ns = (uint32_t)((s + 1) & 1);
            uint4 hi, lo;
            uint4* bA0 = sm + ns*2048 + lr * 8;        uint4* bA1 = bA0 + 512;
            uint4* bB0 = sm + ns*2048 + 1024 + lr * 8; uint4* bB1 = bB0 + 512;
            split_pack(a00, a01, hi, lo); bA0[lc ^ s7] = hi; bA0[(lc+4) ^ s7] = lo;
            split_pack(a10, a11, hi, lo); bA1[lc ^ s7] = hi; bA1[(lc+4) ^ s7] = lo;
            split_pack(b00, b01, hi, lo); bB0[lc ^ s7] = hi; bB0[(lc+4) ^ s7] = lo;
            split_pack(b10, b11, hi, lo); bB1[lc ^ s7] = hi; bB1[(lc+4) ^ s7] = lo;
        }
        __syncthreads();   // single barrier per K-step
    }

    const int g = lane >> 2, tt = lane & 3;
    const long long rowBase = (long long)by * 128 + wm + g;
#pragma unroll
    for (int mf = 0; mf < 4; mf++) {
#pragma unroll
        for (int nf = 0; nf < 4; nf++) {
            const int col = bx * 128 + wn + nf * 8 + 2 * tt;
            float2 bv = make_float2(0.f, 0.f);
            if (bias) bv = *(const float2*)(bias + col);
            float* c0 = C + (long long)bz * sC + (rowBase + mf * 16) * ldc + col;
            float2 v;
            v.x = epi_f(acc[mf][nf][0] * alpha + bv.x, epi);
            v.y = epi_f(acc[mf][nf][1] * alpha + bv.y, epi);
            *(float2*)c0 = v;
            v.x = epi_f(acc[mf][nf][2] * alpha + bv.x, epi);
            v.y = epi_f(acc[mf][nf][3] * alpha + bv.y, epi);
            *(float2*)(c0 + 8LL * ldc) = v;
        }
    }
}

__global__ void transpose_xt(const float* __restrict__ x, float* __restrict__ xt) {
    int gid = blockIdx.x * 256 + threadIdx.x;
    int r = gid >> 5, c = (gid & 31) << 2;
    int b = r / 24576, rem = r - b * 24576, t = rem >> 11, n = rem & 2047;
    float4 v = *(const float4*)(x + (long long)r * 128 + c);
    *(float4*)(xt + ((long long)(b * 2048 + n) * 1536 + t * 128 + c)) = v;
}

__global__ void transpose_v(const float* __restrict__ V, float* __restrict__ VT) {
    __shared__ float tile[32][33];
    int b = blockIdx.z, n0 = blockIdx.x * 32, d0 = blockIdx.y * 32;
    const float* Vb = V + (long long)b * 262144;
    float* VTb = VT + (long long)b * 262144;
    int tx = threadIdx.x & 31, ty = threadIdx.x >> 5;
#pragma unroll
    for (int i = 0; i < 32; i += 8)
        tile[ty + i][tx] = Vb[(long long)(n0 + ty + i) * 128 + d0 + tx];
    __syncthreads();
#pragma unroll
    for (int i = 0; i < 32; i += 8)
        VTb[(long long)(d0 + ty + i) * 2048 + n0 + tx] = tile[tx][ty + i];
}

__global__ void softmax2048(float* __restrict__ S) {
    float* row = S + (long long)blockIdx.x * 2048;
    int t = threadIdx.x;
    float v[8], mx = -3.4e38f;
#pragma unroll
    for (int i = 0; i < 8; i++) { v[i] = row[t + (i << 8)]; mx = fmaxf(mx, v[i]); }
    __shared__ float red[8];
#pragma unroll
    for (int o = 16; o; o >>= 1) mx = fmaxf(mx, __shfl_xor_sync(0xffffffffu, mx, o));
    if ((t & 31) == 0) red[t >> 5] = mx;
    __syncthreads();
    mx = red[0];
#pragma unroll
    for (int i = 1; i < 8; i++) mx = fmaxf(mx, red[i]);
    float s = 0.f;
#pragma unroll
    for (int i = 0; i < 8; i++) { v[i] = __expf(v[i] - mx); s += v[i]; }
#pragma unroll
    for (int o = 16; o; o >>= 1) s += __shfl_xor_sync(0xffffffffu, s, o);
    __syncthreads();
    if ((t & 31) == 0) red[t >> 5] = s;
    __syncthreads();
    s = 0.f;
#pragma unroll
    for (int i = 0; i < 8; i++) s += red[i];
    float inv = 1.f / s;
#pragma unroll
    for (int i = 0; i < 8; i++) row[t + (i << 8)] = v[i] * inv;
}

__global__ void resid_ln(const float* __restrict__ ON, const float* __restrict__ x,
                         const float* __restrict__ gamma, const float* __restrict__ beta,
                         float* __restrict__ HN)
{
    long long r = blockIdx.x;
    int d = threadIdx.x;
    int b = (int)(r / 24576), rem = (int)(r % 24576), t = rem >> 11, n = rem & 2047;
    float v = ON[((long long)(b * 2048 + n)) * 1536 + t * 128 + d] + x[r * 128 + d];
    float s = v, q = v * v;
#pragma unroll
    for (int o = 16; o; o >>= 1) {
        s += __shfl_xor_sync(0xffffffffu, s, o);
        q += __shfl_xor_sync(0xffffffffu, q, o);
    }
    __shared__ float ss[4], qq[4];
    int w = d >> 5, lane = d & 31;
    if (lane == 0) { ss[w] = s; qq[w] = q; }
    __syncthreads();
    s = ss[0] + ss[1] + ss[2] + ss[3];
    q = qq[0] + qq[1] + qq[2] + qq[3];
    float mean = s * (1.f / 128.f);
    float var = q * (1.f / 128.f) - mean * mean;
    float rstd = rsqrtf(var + 1e-5f);
    HN[r * 128 + d] = (v - mean) * rstd * gamma[d] + beta[d];
}

__global__ void dft12(const float* __restrict__ hn,
                      float* __restrict__ re, float* __restrict__ im)
{
    int idx = blockIdx.x * 256 + threadIdx.x;
    int b = idx >> 18, nd = idx & 262143;
    const float* p = hn + (long long)b * 12 * 262144 + nd;
    float vt[12];
#pragma unroll
    for (int t = 0; t < 12; t++) vt[t] = p[(long long)t * 262144];
    const float CT[12] = {1.f, 0.8660254037844386f, 0.5f, 0.f, -0.5f, -0.8660254037844386f,
                          -1.f, -0.8660254037844386f, -0.5f, 0.f, 0.5f, 0.8660254037844386f};
    const float ST[12] = {0.f, 0.5f, 0.8660254037844386f, 1.f, 0.8660254037844386f, 0.5f,
                          0.f, -0.5f, -0.8660254037844386f, -1.f, -0.8660254037844386f, -0.5f};
#pragma unroll
    for (int f = 0; f < 7; f++) {
        float sr = 0.f, si = 0.f;
#pragma unroll
        for (int t = 0; t < 12; t++) {
            int k = (f * t) % 12;
            sr += vt[t] * CT[k];
            si -= vt[t] * ST[k];
        }
        long long o = ((long long)b * 7 + f) * 262144 + nd;
        re[o] = sr; im[o] = si;
    }
}

__global__ void build_wcat(const float* __restrict__ Wr2, const float* __restrict__ br2,
                           const float* __restrict__ Wi2, const float* __restrict__ bi2,
                           float* __restrict__ Wc_r, float* __restrict__ bc_r,
                           float* __restrict__ Wc_i, float* __restrict__ bc_i)
{
    int i = blockIdx.x * 256 + threadIdx.x;
    int n = i >> 8, k = i & 255;
    float vr, vi;
    if (k < 128) { vr = Wr2[n * 128 + k];        vi = Wi2[n * 128 + k]; }
    else         { vr = -Wi2[n * 128 + k - 128]; vi = Wr2[n * 128 + k - 128]; }
    Wc_r[i] = vr; Wc_i[i] = vi;
    if (i < 128) { bc_r[i] = br2[i] - bi2[i]; bc_i[i] = bi2[i] + br2[i]; }
}

__global__ void irfft12(const float* __restrict__ HR, const float* __restrict__ HI,
                        const float* __restrict__ x, float* __restrict__ out)
{
    int idx = blockIdx.x * 256 + threadIdx.x;
    int b = idx >> 18, nd = idx & 262143;
    float hr[7], hi[7];
#pragma unroll
    for (int f = 0; f < 7; f++) {
        long long o = ((long long)b * 7 + f) * 262144 + nd;
        hr[f] = HR[o]; hi[f] = HI[o];
    }
    const float CT[12] = {1.f, 0.8660254037844386f, 0.5f, 0.f, -0.5f, -0.8660254037844386f,
                          -1.f, -0.8660254037844386f, -0.5f, 0.f, 0.5f, 0.8660254037844386f};
    const float ST[12] = {0.f, 0.5f, 0.8660254037844386f, 1.f, 0.8660254037844386f, 0.5f,
                          0.f, -0.5f, -0.8660254037844386f, -1.f, -0.8660254037844386f, -0.5f};
#pragma unroll
    for (int t = 0; t < 12; t++) {
        float acc = hr[0] + ((t & 1) ? -hr[6] : hr[6]);
#pragma unroll
        for (int f = 1; f < 6; f++) {
            int k = (f * t) % 12;
            acc += 2.f * (hr[f] * CT[k] - hi[f] * ST[k]);
        }
        long long o = ((long long)b * 12 + t) * 262144 + nd;
        out[o] = x[o] + acc * (1.f / 12.f);
    }
}

extern "C" void kernel_launch(void* const* d_in, const int* in_sizes, int n_in,
                              void* d_out, int out_size)
{
    const float* x   = (const float*)d_in[0];
    const float* Wd1 = (const float*)d_in[1];  const float* bd1 = (const float*)d_in[2];
    const float* Wd2 = (const float*)d_in[3];  const float* bd2 = (const float*)d_in[4];
    const float* Wq  = (const float*)d_in[5];  const float* bq  = (const float*)d_in[6];
    const float* Wk  = (const float*)d_in[7];  const float* bk  = (const float*)d_in[8];
    const float* Wv  = (const float*)d_in[9];  const float* bv  = (const float*)d_in[10];
    const float* Wu1 = (const float*)d_in[11]; const float* bu1 = (const float*)d_in[12];
    const float* Wu2 = (const float*)d_in[13]; const float* bu2 = (const float*)d_in[14];
    const float* gamma = (const float*)d_in[15];
    const float* beta  = (const float*)d_in[16];
    const float* Wr1 = (const float*)d_in[17]; const float* br1 = (const float*)d_in[18];
    const float* Wr2 = (const float*)d_in[19]; const float* br2 = (const float*)d_in[20];
    const float* Wi1 = (const float*)d_in[21]; const float* bi1 = (const float*)d_in[22];
    const float* Wi2 = (const float*)d_in[23]; const float* bi2 = (const float*)d_in[24];
    float* out = (float*)d_out;

    float* arena = nullptr;
    cudaGetSymbolAddress((void**)&arena, g_arena);

    float* XT = arena + OFF_XT;   float* U  = XT;
    float* S  = arena + OFF_S;    float* ON = S;
    float* H1 = arena + OFF_H1;
    float* Y  = arena + OFF_Y;
    float* Q  = arena + OFF_Q;
    float* Km = arena + OFF_K;
    float* V  = arena + OFF_V;
    float* VT = arena + OFF_VT;
    float* O  = arena + OFF_O;
    float* HN = arena + OFF_HN;
    float* RE = arena + OFF_RE;   float* HR = RE;
    float* IM = arena + OFF_IM;   float* HI = IM;
    float* Hrc = arena + OFF_HRC;
    float* Hic = arena + OFF_HIC;
    float* WCR = arena + OFF_WCR; float* WCI = arena + OFF_WCI;
    float* BCR = arena + OFF_BCR; float* BCI = arena + OFF_BCI;

    cudaFuncSetAttribute(gemm_bf16x3, cudaFuncAttributeMaxDynamicSharedMemorySize, 65536);

    // ---- node branch ----
    transpose_xt<<<49152, 256>>>(x, XT);
    gemm_bf16x3<<<dim3(1, 256, 1), 256, 65536>>>(XT, Wd1, bd1, H1, 1536, 128, 1.f, 1, 0, 0, 0);
    gemm_bf16x3<<<dim3(1, 256, 1), 256, 65536>>>(H1, Wd2, bd2, Y, 128, 128, 1.f, 0, 0, 0, 0);
    gemm_bf16x3<<<dim3(1, 256, 1), 256, 65536>>>(Y, Wq, bq, Q, 128, 128, 1.f, 0, 0, 0, 0);
    gemm_bf16x3<<<dim3(1, 256, 1), 256, 65536>>>(Y, Wk, bk, Km, 128, 128, 1.f, 0, 0, 0, 0);
    gemm_bf16x3<<<dim3(1, 256, 1), 256, 65536>>>(Y, Wv, bv, V, 128, 128, 1.f, 0, 0, 0, 0);

    // ---- attention ----
    gemm_bf16x3<<<dim3(16, 16, 16), 256, 65536>>>(Q, Km, nullptr, S, 128, 2048, 0.125f, 0,
                                                  262144, 262144, 4194304);
    softmax2048<<<32768, 256>>>(S);
    transpose_v<<<dim3(64, 4, 16), 256>>>(V, VT);
    gemm_bf16x3<<<dim3(1, 16, 16), 256, 65536>>>(S, VT, nullptr, O, 2048, 128, 1.f, 0,
                                                 4194304, 262144, 262144);

    // ---- conv_up ----
    gemm_bf16x3<<<dim3(12, 256, 1), 256, 65536>>>(O, Wu1, bu1, U, 128, 1536, 1.f, 1, 0, 0, 0);
    gemm_bf16x3<<<dim3(12, 256, 1), 256, 65536>>>(U, Wu2, bu2, ON, 1536, 1536, 1.f, 0, 0, 0, 0);

    // ---- residual + LN, rfft ----
    resid_ln<<<786432, 128>>>(ON, x, gamma, beta, HN);
    dft12<<<16384, 256>>>(HN, RE, IM);
    build_wcat<<<128, 256>>>(Wr2, br2, Wi2, bi2, WCR, BCR, WCI, BCI);

    // ---- fused FFT dual-path MLP ----
    gemm_bf16x3<<<dim3(1, 1792, 1), 256, 65536>>>(RE, Wr1, br1, Hrc,       128, 256, 1.f, 2, 0, 0, 0);
    gemm_bf16x3<<<dim3(1, 1792, 1), 256, 65536>>>(IM, Wi1, bi1, Hrc + 128, 128, 256, 1.f, 2, 0, 0, 0);
    gemm_bf16x3<<<dim3(1, 1792, 1), 256, 65536>>>(RE, Wi1, bi1, Hic,       128, 256, 1.f, 2, 0, 0, 0);
    gemm_bf16x3<<<dim3(1, 1792, 1), 256, 65536>>>(IM, Wr1, br1, Hic + 128, 128, 256, 1.f, 2, 0, 0, 0);
    gemm_bf16x3<<<dim3(1, 1792, 1), 256, 65536>>>(Hrc, WCR, BCR, HR, 256, 128, 1.f, 0, 0, 0, 0);
    gemm_bf16x3<<<dim3(1, 1792, 1), 256, 65536>>>(Hic, WCI, BCI, HI, 256, 128, 1.f, 0, 0, 0, 0);

    // ---- irfft + residual ----
    irfft12<<<16384, 256>>>(HR, HI, x, out);
}

// round 11
// speedup vs baseline: 2.0356x; 1.0827x over previous
#include <cuda_runtime.h>
#include <cuda_bf16.h>
#include <stdint.h>
#include <math.h>

// B=16, T=12, N=2048, D=128.  x: [16,12,2048,128] f32
static const long long OFF_S   = 50331648LL;   // S [16,2048,2048] (alias ON)
static const long long OFF_H1  = 117440512LL;  // H1 [32768,128]
static const long long OFF_QKV = 121634816LL;  // QKV [32768,384] (12582912)
static const long long OFF_VT  = 138412032LL;  // VT [16,128,2048]
static const long long OFF_O   = 142606336LL;  // O  [16,2048,128]
static const long long OFF_RE  = 197132288LL;  // RE [16,7,2048,128] (alias HR)
static const long long OFF_IM  = 226492416LL;  // IM (alias HI)
static const long long OFF_H2  = 255852544LL;  // H2 [229376,512] = 117440512
static const long long OFF_WCR = 373293056LL;  // [128,256]
static const long long OFF_WCI = 373325824LL;
static const long long OFF_BCR = 373358592LL;
static const long long OFF_BCI = 373358720LL;
static const long long OFF_W1A = 373358848LL;  // [256,128]
static const long long OFF_W1B = 373391616LL;
static const long long OFF_B1A = 373424384LL;  // [256]
static const long long OFF_B1B = 373424640LL;
static const long long OFF_WQKV= 373424896LL;  // [384,128]
static const long long OFF_BQKV= 373474048LL;  // [384]

__device__ float g_arena[373474432];

__device__ __forceinline__ float epi_f(float v, int epi) {
    if (epi == 1) return v > 0.f ? v : 0.f;
    if (epi == 2) return 0.5f * v * (1.f + erff(v * 0.7071067811865476f));
    return v;
}

__device__ __forceinline__ void ldsm4(uint32_t &r0, uint32_t &r1, uint32_t &r2, uint32_t &r3,
                                      uint32_t addr) {
    asm volatile("ldmatrix.sync.aligned.m8n8.x4.shared.b16 {%0,%1,%2,%3}, [%4];"
                 : "=r"(r0), "=r"(r1), "=r"(r2), "=r"(r3) : "r"(addr));
}
__device__ __forceinline__ void mma_bf16(float* d, const uint32_t* a, const uint32_t* b) {
    asm volatile("mma.sync.aligned.m16n8k16.row.col.f32.bf16.bf16.f32 "
                 "{%0,%1,%2,%3}, {%4,%5,%6,%7}, {%8,%9}, {%0,%1,%2,%3};"
                 : "+f"(d[0]), "+f"(d[1]), "+f"(d[2]), "+f"(d[3])
                 : "r"(a[0]), "r"(a[1]), "r"(a[2]), "r"(a[3]), "r"(b[0]), "r"(b[1]));
}

__device__ __forceinline__ void split_pack(float4 v0, float4 v1, uint4 &hi, uint4 &lo) {
    float f[8] = {v0.x, v0.y, v0.z, v0.w, v1.x, v1.y, v1.z, v1.w};
    uint32_t h[4], l[4];
#pragma unroll
    for (int i = 0; i < 4; i++) {
        __nv_bfloat16 h0 = __float2bfloat16_rn(f[2*i]);
        __nv_bfloat16 h1 = __float2bfloat16_rn(f[2*i+1]);
        __nv_bfloat16 l0 = __float2bfloat16_rn(f[2*i]   - __bfloat162float(h0));
        __nv_bfloat16 l1 = __float2bfloat16_rn(f[2*i+1] - __bfloat162float(h1));
        h[i] = ((uint32_t)__bfloat16_as_ushort(h1) << 16) | (uint32_t)__bfloat16_as_ushort(h0);
        l[i] = ((uint32_t)__bfloat16_as_ushort(l1) << 16) | (uint32_t)__bfloat16_as_ushort(l0);
    }
    hi = make_uint4(h[0], h[1], h[2], h[3]);
    lo = make_uint4(l[0], l[1], l[2], l[3]);
}

// x[B,T,N,D] gather: logical A row=(b*2048+n), col k=(t*128+d)
__device__ __forceinline__ const float* xgather_ptr(const float* X, int row, int k) {
    int t = k >> 7, d = k & 127, b = row >> 11, n = row & 2047;
    return X + ((long long)(b * 12 + t) * 2048 + n) * 128 + d;
}

// C = epi(alpha * A @ B^T + bias). A:[M,K] row stride lda (amode1: gather from x),
// B:[N,K] row stride ldb. C col = bx*colstep + (0..127), row stride ldc.
// bias indexed by logical N (bx*128+..). grid.y=M/128, grid.x=N/128, K%32==0.
// 256 threads, 64KB dyn smem, double-buffered.
__global__ void __launch_bounds__(256)
gemm_bf16x3(const float* __restrict__ A, const float* __restrict__ B,
            const float* __restrict__ bias, float* __restrict__ C,
            int K, int lda, int ldb, int ldc, int colstep, float alpha, int epi, int amode,
            long long sA, long long sB, long long sC)
{
    extern __shared__ __align__(16) uint4 sm[];
    const int t = threadIdx.x;
    const int bx = blockIdx.x, by = blockIdx.y, bz = blockIdx.z;
    const int lane = t & 31;

    const int lr = t >> 2, lc = t & 3, s7 = lr & 7;
    const float* Ag0 = A + (long long)bz * sA + (long long)(by * 128 + lr) * lda + lc * 8;
    const float* Ag1 = Ag0 + (long long)64 * lda;
    const float* Bg0 = B + (long long)bz * sB + (long long)(bx * 128 + lr) * ldb + lc * 8;
    const float* Bg1 = Bg0 + (long long)64 * ldb;

    const int sub = lane >> 3, l7 = lane & 7;
    const int wm = (t >> 7) * 64, wn = ((t >> 5) & 3) * 32;
    const int aRowOff = wm + l7 + ((sub & 1) << 3);
    const int aSel = sub >> 1;
    const int bRowOff = wn + l7 + ((sub >> 1) << 3);
    const int bSel = sub & 1;
    const uint32_t smemBase = (uint32_t)__cvta_generic_to_shared(sm);

    float acc[4][4][4];
#pragma unroll
    for (int i = 0; i < 4; i++)
#pragma unroll
        for (int j = 0; j < 4; j++)
#pragma unroll
            for (int q = 0; q < 4; q++) acc[i][j][q] = 0.f;

    const int nk = K >> 5;
    {   // tile 0 -> buffer 0
        const float *pa0, *pa1;
        if (amode == 0) { pa0 = Ag0; pa1 = Ag1; }
        else { pa0 = xgather_ptr(A, by*128 + lr, lc*8);
               pa1 = xgather_ptr(A, by*128 + lr + 64, lc*8); }
        uint4 hi, lo;
        uint4* bA0 = sm + lr * 8;        uint4* bA1 = bA0 + 512;
        uint4* bB0 = sm + 1024 + lr * 8; uint4* bB1 = bB0 + 512;
        split_pack(*(const float4*)pa0, *(const float4*)(pa0+4), hi, lo);
        bA0[lc ^ s7] = hi; bA0[(lc+4) ^ s7] = lo;
        split_pack(*(const float4*)pa1, *(const float4*)(pa1+4), hi, lo);
        bA1[lc ^ s7] = hi; bA1[(lc+4) ^ s7] = lo;
        split_pack(*(const float4*)Bg0, *(const float4*)(Bg0+4), hi, lo);
        bB0[lc ^ s7] = hi; bB0[(lc+4) ^ s7] = lo;
        split_pack(*(const float4*)Bg1, *(const float4*)(Bg1+4), hi, lo);
        bB1[lc ^ s7] = hi; bB1[(lc+4) ^ s7] = lo;
    }
    __syncthreads();

    for (int s = 0; s < nk; s++) {
        float4 a00, a01, a10, a11, b00, b01, b10, b11;
        const bool more = (s + 1) < nk;
        if (more) {
            const float *pa0, *pa1;
            if (amode == 0) { pa0 = Ag0 + (s+1)*32; pa1 = Ag1 + (s+1)*32; }
            else { pa0 = xgather_ptr(A, by*128 + lr, (s+1)*32 + lc*8);
                   pa1 = xgather_ptr(A, by*128 + lr + 64, (s+1)*32 + lc*8); }
            const float* pb0 = Bg0 + (s+1)*32; const float* pb1 = Bg1 + (s+1)*32;
            a00 = *(const float4*)pa0; a01 = *(const float4*)(pa0+4);
            a10 = *(const float4*)pa1; a11 = *(const float4*)(pa1+4);
            b00 = *(const float4*)pb0; b01 = *(const float4*)(pb0+4);
            b10 = *(const float4*)pb1; b11 = *(const float4*)(pb1+4);
        }
        const uint32_t stg = smemBase + (uint32_t)(s & 1) * 32768u;
#pragma unroll
        for (int kh = 0; kh < 2; kh++) {
            uint32_t ah[4][4], al[4][4], bh[4][2], bl[4][2];
#pragma unroll
            for (int mf = 0; mf < 4; mf++) {
                const uint32_t rb = stg + (uint32_t)(aRowOff + mf * 16) * 128;
                const int u0 = 2 * kh + aSel;
                ldsm4(ah[mf][0], ah[mf][1], ah[mf][2], ah[mf][3], rb + ((u0 ^ l7) << 4));
                ldsm4(al[mf][0], al[mf][1], al[mf][2], al[mf][3], rb + (((u0 + 4) ^ l7) << 4));
            }
#pragma unroll
            for (int np = 0; np < 2; np++) {
                const uint32_t rb = stg + 16384 + (uint32_t)(bRowOff + np * 16) * 128;
                const int u0 = 2 * kh + bSel;
                uint32_t r0, r1, r2, r3;
                ldsm4(r0, r1, r2, r3, rb + ((u0 ^ l7) << 4));
                bh[np*2][0] = r0; bh[np*2][1] = r1; bh[np*2+1][0] = r2; bh[np*2+1][1] = r3;
                ldsm4(r0, r1, r2, r3, rb + (((u0 + 4) ^ l7) << 4));
                bl[np*2][0] = r0; bl[np*2][1] = r1; bl[np*2+1][0] = r2; bl[np*2+1][1] = r3;
            }
#pragma unroll
            for (int mf = 0; mf < 4; mf++)
#pragma unroll
                for (int nf = 0; nf < 4; nf++) {
                    mma_bf16(acc[mf][nf], ah[mf], bh[nf]);
                    mma_bf16(acc[mf][nf], ah[mf], bl[nf]);
                    mma_bf16(acc[mf][nf], al[mf], bh[nf]);
                }
        }
        if (more) {
            const uint32_t ns = (uint32_t)((s + 1) & 1);
            uint4 hi, lo;
            uint4* bA0 = sm + ns*2048 + lr * 8;        uint4* bA1 = bA0 + 512;
            uint4* bB0 = sm + ns*2048 + 1024 + lr * 8; uint4* bB1 = bB0 + 512;
            split_pack(a00, a01, hi, lo); bA0[lc ^ s7] = hi; bA0[(lc+4) ^ s7] = lo;
            split_pack(a10, a11, hi, lo); bA1[lc ^ s7] = hi; bA1[(lc+4) ^ s7] = lo;
            split_pack(b00, b01, hi, lo); bB0[lc ^ s7] = hi; bB0[(lc+4) ^ s7] = lo;
            split_pack(b10, b11, hi, lo); bB1[lc ^ s7] = hi; bB1[(lc+4) ^ s7] = lo;
        }
        __syncthreads();
    }

    const int g = lane >> 2, tt = lane & 3;
    const long long rowBase = (long long)by * 128 + wm + g;
#pragma unroll
    for (int mf = 0; mf < 4; mf++) {
#pragma unroll
        for (int nf = 0; nf < 4; nf++) {
            const int nIdx = bx * 128 + wn + nf * 8 + 2 * tt;
            const int col = bx * colstep + wn + nf * 8 + 2 * tt;
            float2 bv = make_float2(0.f, 0.f);
            if (bias) bv = *(const float2*)(bias + nIdx);
            float* c0 = C + (long long)bz * sC + (rowBase + mf * 16) * ldc + col;
            float2 v;
            v.x = epi_f(acc[mf][nf][0] * alpha + bv.x, epi);
            v.y = epi_f(acc[mf][nf][1] * alpha + bv.y, epi);
            *(float2*)c0 = v;
            v.x = epi_f(acc[mf][nf][2] * alpha + bv.x, epi);
            v.y = epi_f(acc[mf][nf][3] * alpha + bv.y, epi);
            *(float2*)(c0 + 8LL * ldc) = v;
        }
    }
}

// fold Wd2 into QKV: WQKV[i,k] = sum_c Wsel[i,c]*Wd2[c,k]; BQKV[i] = sum_c Wsel[i,c]*bd2[c] + bsel[i]
__global__ void wqkv_fold(const float* __restrict__ Wq, const float* __restrict__ bq,
                          const float* __restrict__ Wk, const float* __restrict__ bk,
                          const float* __restrict__ Wv, const float* __restrict__ bv,
                          const float* __restrict__ Wd2, const float* __restrict__ bd2,
                          float* __restrict__ WQKV, float* __restrict__ BQKV)
{
    int i = blockIdx.x, j = threadIdx.x;
    const float* row = (i < 128) ? Wq + i * 128 : (i < 256) ? Wk + (i - 128) * 128 : Wv + (i - 256) * 128;
    float bo = (i < 128) ? bq[i] : (i < 256) ? bk[i - 128] : bv[i - 256];
    float acc = 0.f, accb = 0.f;
    for (int c = 0; c < 128; c++) {
        float w = row[c];
        acc += w * Wd2[c * 128 + j];
        accb += w * bd2[c];
    }
    WQKV[i * 128 + j] = acc;
    if (j == 0) BQKV[i] = accb + bo;
}

// layer-1 stacked weights: W1A=[Wr1;Wi1], b1a=[br1;bi1]; W1B=[Wi1;Wr1], b1b=[bi1;br1]
__global__ void build_w1(const float* __restrict__ Wr1, const float* __restrict__ br1,
                         const float* __restrict__ Wi1, const float* __restrict__ bi1,
                         float* __restrict__ W1A, float* __restrict__ b1a,
                         float* __restrict__ W1B, float* __restrict__ b1b)
{
    int i = blockIdx.x * 256 + threadIdx.x;   // < 32768
    int r = i >> 7, c = i & 127;
    W1A[i] = (r < 128) ? Wr1[r * 128 + c] : Wi1[(r - 128) * 128 + c];
    W1B[i] = (r < 128) ? Wi1[r * 128 + c] : Wr1[(r - 128) * 128 + c];
    if (i < 256) {
        b1a[i] = (i < 128) ? br1[i] : bi1[i - 128];
        b1b[i] = (i < 128) ? bi1[i] : br1[i - 128];
    }
}

// layer-2 concat weights: WCR=[Wr2|-Wi2], bcr=br2-bi2; WCI=[Wi2|Wr2], bci=bi2+br2
__global__ void build_wcat(const float* __restrict__ Wr2, const float* __restrict__ br2,
                           const float* __restrict__ Wi2, const float* __restrict__ bi2,
                           float* __restrict__ Wc_r, float* __restrict__ bc_r,
                           float* __restrict__ Wc_i, float* __restrict__ bc_i)
{
    int i = blockIdx.x * 256 + threadIdx.x;
    int n = i >> 8, k = i & 255;
    float vr, vi;
    if (k < 128) { vr = Wr2[n * 128 + k];        vi = Wi2[n * 128 + k]; }
    else         { vr = -Wi2[n * 128 + k - 128]; vi = Wr2[n * 128 + k - 128]; }
    Wc_r[i] = vr; Wc_i[i] = vi;
    if (i < 128) { bc_r[i] = br2[i] - bi2[i]; bc_i[i] = bi2[i] + br2[i]; }
}

__global__ void transpose_v(const float* __restrict__ QKV, float* __restrict__ VT) {
    __shared__ float tile[32][33];
    int b = blockIdx.z, n0 = blockIdx.x * 32, d0 = blockIdx.y * 32;
    float* VTb = VT + (long long)b * 262144;
    int tx = threadIdx.x & 31, ty = threadIdx.x >> 5;
#pragma unroll
    for (int i = 0; i < 32; i += 8)
        tile[ty + i][tx] = QKV[((long long)b * 2048 + n0 + ty + i) * 384 + 256 + d0 + tx];
    __syncthreads();
#pragma unroll
    for (int i = 0; i < 32; i += 8)
        VTb[(long long)(d0 + ty + i) * 2048 + n0 + tx] = tile[tx][ty + i];
}

__global__ void softmax2048(float* __restrict__ S) {
    float* row = S + (long long)blockIdx.x * 2048;
    int t = threadIdx.x;
    float v[8], mx = -3.4e38f;
#pragma unroll
    for (int i = 0; i < 8; i++) { v[i] = row[t + (i << 8)]; mx = fmaxf(mx, v[i]); }
    __shared__ float red[8];
#pragma unroll
    for (int o = 16; o; o >>= 1) mx = fmaxf(mx, __shfl_xor_sync(0xffffffffu, mx, o));
    if ((t & 31) == 0) red[t >> 5] = mx;
    __syncthreads();
    mx = red[0];
#pragma unroll
    for (int i = 1; i < 8; i++) mx = fmaxf(mx, red[i]);
    float s = 0.f;
#pragma unroll
    for (int i = 0; i < 8; i++) { v[i] = __expf(v[i] - mx); s += v[i]; }
#pragma unroll
    for (int o = 16; o; o >>= 1) s += __shfl_xor_sync(0xffffffffu, s, o);
    __syncthreads();
    if ((t & 31) == 0) red[t >> 5] = s;
    __syncthreads();
    s = 0.f;
#pragma unroll
    for (int i = 0; i < 8; i++) s += red[i];
    float inv = 1.f / s;
#pragma unroll
    for (int i = 0; i < 8; i++) row[t + (i << 8)] = v[i] * inv;
}

// fused: residual add + LayerNorm (per t) + 12-point rDFT over t.
// ON [B,N,T*D] (conv_up layout), x [B,T,N,D]; out RE/IM [B,7,N,D].
__global__ void ln_dft(const float* __restrict__ ON, const float* __restrict__ x,
                       const float* __restrict__ gamma, const float* __restrict__ beta,
                       float* __restrict__ re, float* __restrict__ im)
{
    int bn = blockIdx.x;                 // b*2048+n
    int d = threadIdx.x;
    int b = bn >> 11, n = bn & 2047;
    float v[12];
    const float* onp = ON + (long long)bn * 1536 + d;
    const float* xp = x + ((long long)(b * 12) * 2048 + n) * 128 + d;
#pragma unroll
    for (int t = 0; t < 12; t++) v[t] = onp[t * 128] + xp[(long long)t * 262144];

    __shared__ float sred[12][4], qred[12][4];
    int w = d >> 5, lane = d & 31;
#pragma unroll
    for (int t = 0; t < 12; t++) {
        float s = v[t], q = v[t] * v[t];
#pragma unroll
        for (int o = 16; o; o >>= 1) {
            s += __shfl_xor_sync(0xffffffffu, s, o);
            q += __shfl_xor_sync(0xffffffffu, q, o);
        }
        if (lane == 0) { sred[t][w] = s; qred[t][w] = q; }
    }
    __syncthreads();
    float g = gamma[d], be = beta[d];
#pragma unroll
    for (int t = 0; t < 12; t++) {
        float s = sred[t][0] + sred[t][1] + sred[t][2] + sred[t][3];
        float q = qred[t][0] + qred[t][1] + qred[t][2] + qred[t][3];
        float mu = s * (1.f / 128.f);
        float var = q * (1.f / 128.f) - mu * mu;
        v[t] = (v[t] - mu) * rsqrtf(var + 1e-5f) * g + be;
    }
    const float CT[12] = {1.f, 0.8660254037844386f, 0.5f, 0.f, -0.5f, -0.8660254037844386f,
                          -1.f, -0.8660254037844386f, -0.5f, 0.f, 0.5f, 0.8660254037844386f};
    const float ST[12] = {0.f, 0.5f, 0.8660254037844386f, 1.f, 0.8660254037844386f, 0.5f,
                          0.f, -0.5f, -0.8660254037844386f, -1.f, -0.8660254037844386f, -0.5f};
#pragma unroll
    for (int f = 0; f < 7; f++) {
        float sr = 0.f, si = 0.f;
#pragma unroll
        for (int t = 0; t < 12; t++) {
            int k = (f * t) % 12;
            sr += v[t] * CT[k];
            si -= v[t] * ST[k];
        }
        long long o = ((long long)(b * 7 + f)) * 262144 + n * 128 + d;
        re[o] = sr; im[o] = si;
    }
}

__global__ void irfft12(const float* __restrict__ HR, const float* __restrict__ HI,
                        const float* __restrict__ x, float* __restrict__ out)
{
    int idx = blockIdx.x * 256 + threadIdx.x;
    int b = idx >> 18, nd = idx & 262143;
    float hr[7], hi[7];
#pragma unroll
    for (int f = 0; f < 7; f++) {
        long long o = ((long long)b * 7 + f) * 262144 + nd;
        hr[f] = HR[o]; hi[f] = HI[o];
    }
    const float CT[12] = {1.f, 0.8660254037844386f, 0.5f, 0.f, -0.5f, -0.8660254037844386f,
                          -1.f, -0.8660254037844386f, -0.5f, 0.f, 0.5f, 0.8660254037844386f};
    const float ST[12] = {0.f, 0.5f, 0.8660254037844386f, 1.f, 0.8660254037844386f, 0.5f,
                          0.f, -0.5f, -0.8660254037844386f, -1.f, -0.8660254037844386f, -0.5f};
#pragma unroll
    for (int t = 0; t < 12; t++) {
        float acc = hr[0] + ((t & 1) ? -hr[6] : hr[6]);
#pragma unroll
        for (int f = 1; f < 6; f++) {
            int k = (f * t) % 12;
            acc += 2.f * (hr[f] * CT[k] - hi[f] * ST[k]);
        }
        long long o = ((long long)b * 12 + t) * 262144 + nd;
        out[o] = x[o] + acc * (1.f / 12.f);
    }
}

extern "C" void kernel_launch(void* const* d_in, const int* in_sizes, int n_in,
                              void* d_out, int out_size)
{
    const float* x   = (const float*)d_in[0];
    const float* Wd1 = (const float*)d_in[1];  const float* bd1 = (const float*)d_in[2];
    const float* Wd2 = (const float*)d_in[3];  const float* bd2 = (const float*)d_in[4];
    const float* Wq  = (const float*)d_in[5];  const float* bq  = (const float*)d_in[6];
    const float* Wk  = (const float*)d_in[7];  const float* bk  = (const float*)d_in[8];
    const float* Wv  = (const float*)d_in[9];  const float* bv  = (const float*)d_in[10];
    const float* Wu1 = (const float*)d_in[11]; const float* bu1 = (const float*)d_in[12];
    const float* Wu2 = (const float*)d_in[13]; const float* bu2 = (const float*)d_in[14];
    const float* gamma = (const float*)d_in[15];
    const float* beta  = (const float*)d_in[16];
    const float* Wr1 = (const float*)d_in[17]; const float* br1 = (const float*)d_in[18];
    const float* Wr2 = (const float*)d_in[19]; const float* br2 = (const float*)d_in[20];
    const float* Wi1 = (const float*)d_in[21]; const float* bi1 = (const float*)d_in[22];
    const float* Wi2 = (const float*)d_in[23]; const float* bi2 = (const float*)d_in[24];
    float* out = (float*)d_out;

    float* arena = nullptr;
    cudaGetSymbolAddress((void**)&arena, g_arena);

    float* S   = arena + OFF_S;    float* ON = S;    // aliased
    float* H1  = arena + OFF_H1;
    float* QKV = arena + OFF_QKV;
    float* VT  = arena + OFF_VT;
    float* O   = arena + OFF_O;
    float* RE  = arena + OFF_RE;   float* HR = RE;
    float* IM  = arena + OFF_IM;   float* HI = IM;
    float* H2  = arena + OFF_H2;
    float* WCR = arena + OFF_WCR;  float* WCI = arena + OFF_WCI;
    float* BCR = arena + OFF_BCR;  float* BCI = arena + OFF_BCI;
    float* W1A = arena + OFF_W1A;  float* W1B = arena + OFF_W1B;
    float* B1A = arena + OFF_B1A;  float* B1B = arena + OFF_B1B;
    float* WQKVp = arena + OFF_WQKV;
    float* BQKVp = arena + OFF_BQKV;

    cudaFuncSetAttribute(gemm_bf16x3, cudaFuncAttributeMaxDynamicSharedMemorySize, 65536);

    // ---- weight preprocessing ----
    wqkv_fold<<<384, 128>>>(Wq, bq, Wk, bk, Wv, bv, Wd2, bd2, WQKVp, BQKVp);
    build_w1<<<128, 256>>>(Wr1, br1, Wi1, bi1, W1A, B1A, W1B, B1B);
    build_wcat<<<128, 256>>>(Wr2, br2, Wi2, bi2, WCR, BCR, WCI, BCI);

    // ---- node branch: conv_down G1 (x gathered directly) -> H1, then fused QKV ----
    gemm_bf16x3<<<dim3(1, 256, 1), 256, 65536>>>(x, Wd1, bd1, H1,
        1536, 0, 1536, 128, 128, 1.f, 1, 1, 0, 0, 0);
    gemm_bf16x3<<<dim3(3, 256, 1), 256, 65536>>>(H1, WQKVp, BQKVp, QKV,
        128, 128, 128, 384, 128, 1.f, 0, 0, 0, 0, 0);

    // ---- attention ----
    gemm_bf16x3<<<dim3(16, 16, 16), 256, 65536>>>(QKV, QKV + 128, nullptr, S,
        128, 384, 384, 2048, 128, 0.125f, 0, 0, 786432, 786432, 4194304);
    softmax2048<<<32768, 256>>>(S);
    transpose_v<<<dim3(64, 4, 16), 256>>>(QKV, VT);
    gemm_bf16x3<<<dim3(1, 16, 16), 256, 65536>>>(S, VT, nullptr, O,
        2048, 2048, 2048, 128, 128, 1.f, 0, 0, 4194304, 262144, 262144);

    // ---- conv_up ----
    gemm_bf16x3<<<dim3(12, 256, 1), 256, 65536>>>(O, Wu1, bu1, arena /*U at OFF 0*/,
        128, 128, 128, 1536, 128, 1.f, 1, 0, 0, 0, 0);
    gemm_bf16x3<<<dim3(12, 256, 1), 256, 65536>>>(arena, Wu2, bu2, ON,
        1536, 1536, 1536, 1536, 128, 1.f, 0, 0, 0, 0, 0);

    // ---- fused residual + LN + rfft ----
    ln_dft<<<32768, 128>>>(ON, x, gamma, beta, RE, IM);

    // ---- FFT dual-path MLP: layer1 (2 merged GEMMs), layer2 (2 GEMMs) ----
    gemm_bf16x3<<<dim3(2, 1792, 1), 256, 65536>>>(RE, W1A, B1A, H2,
        128, 128, 128, 512, 256, 1.f, 2, 0, 0, 0, 0);
    gemm_bf16x3<<<dim3(2, 1792, 1), 256, 65536>>>(IM, W1B, B1B, H2 + 128,
        128, 128, 128, 512, 256, 1.f, 2, 0, 0, 0, 0);
    gemm_bf16x3<<<dim3(1, 1792, 1), 256, 65536>>>(H2, WCR, BCR, HR,
        256, 512, 256, 128, 128, 1.f, 0, 0, 0, 0, 0);
    gemm_bf16x3<<<dim3(1, 1792, 1), 256, 65536>>>(H2 + 256, WCI, BCI, HI,
        256, 512, 256, 128, 128, 1.f, 0, 0, 0, 0, 0);

    // ---- irfft + residual ----
    irfft12<<<16384, 256>>>(HR, HI, x, out);
}

// round 12
// speedup vs baseline: 2.6120x; 1.2831x over previous
#include <cuda_runtime.h>
#include <cuda_bf16.h>
#include <stdint.h>
#include <math.h>

typedef __nv_bfloat16 bf16;

// B=16,T=12,N=2048,D=128. Arena offsets (float units). Planes: hi then lo (bf16).
static const long long OFF_S   = 0;            // S f32 67108864 ; then Up planes
static const long long OFF_SP  = 67108864LL;   // SP planes ; then ON f32
static const long long OFF_H1P = 134217728LL;
static const long long OFF_QKVP= 138412032LL;
static const long long OFF_VTP = 150994944LL;
static const long long OFF_OP  = 155189248LL;
static const long long OFF_REP = 159383552LL;  // later HR f32
static const long long OFF_IMP = 188743680LL;  // later HI f32
static const long long OFF_H2P = 218103808LL;  // 117440512
static const long long OFF_WQKVP=335544320LL;
static const long long OFF_BQKV =335593472LL;
static const long long OFF_WU1P =335593856LL;
static const long long OFF_WU2P =335790464LL;
static const long long OFF_W1AP =338149760LL;
static const long long OFF_W1BP =338182528LL;
static const long long OFF_B1A  =338215296LL;
static const long long OFF_B1B  =338215552LL;
static const long long OFF_WCRP =338215808LL;
static const long long OFF_WCIP =338248576LL;
static const long long OFF_BCR  =338281344LL;
static const long long OFF_BCI  =338281472LL;

__device__ float g_arena[338282496];

__device__ __forceinline__ float epi_f(float v, int epi) {
    if (epi == 1) return v > 0.f ? v : 0.f;
    if (epi == 2) return 0.5f * v * (1.f + erff(v * 0.7071067811865476f));
    return v;
}
__device__ __forceinline__ void split1(float a, bf16& h, bf16& l) {
    h = __float2bfloat16_rn(a);
    l = __float2bfloat16_rn(a - __bfloat162float(h));
}
__device__ __forceinline__ void split2(float a, float b, uint32_t& h, uint32_t& l) {
    bf16 ha, la, hb, lb;
    split1(a, ha, la); split1(b, hb, lb);
    h = (uint32_t)__bfloat16_as_ushort(ha) | ((uint32_t)__bfloat16_as_ushort(hb) << 16);
    l = (uint32_t)__bfloat16_as_ushort(la) | ((uint32_t)__bfloat16_as_ushort(lb) << 16);
}
__device__ __forceinline__ void ldsm4(uint32_t &r0, uint32_t &r1, uint32_t &r2, uint32_t &r3,
                                      uint32_t addr) {
    asm volatile("ldmatrix.sync.aligned.m8n8.x4.shared.b16 {%0,%1,%2,%3}, [%4];"
                 : "=r"(r0), "=r"(r1), "=r"(r2), "=r"(r3) : "r"(addr));
}
__device__ __forceinline__ void mma_bf16(float* d, const uint32_t* a, const uint32_t* b) {
    asm volatile("mma.sync.aligned.m16n8k16.row.col.f32.bf16.bf16.f32 "
                 "{%0,%1,%2,%3}, {%4,%5,%6,%7}, {%8,%9}, {%0,%1,%2,%3};"
                 : "+f"(d[0]), "+f"(d[1]), "+f"(d[2]), "+f"(d[3])
                 : "r"(a[0]), "r"(a[1]), "r"(a[2]), "r"(a[3]), "r"(b[0]), "r"(b[1]));
}
__device__ __forceinline__ void cpa16(uint32_t dst, const void* src) {
    asm volatile("cp.async.cg.shared.global [%0], [%1], 16;" :: "r"(dst), "l"(src));
}
__device__ __forceinline__ void split_pack(float4 v0, float4 v1, uint4 &hi, uint4 &lo) {
    float f[8] = {v0.x, v0.y, v0.z, v0.w, v1.x, v1.y, v1.z, v1.w};
    uint32_t h[4], l[4];
#pragma unroll
    for (int i = 0; i < 4; i++) split2(f[2*i], f[2*i+1], h[i], l[i]);
    hi = make_uint4(h[0], h[1], h[2], h[3]);
    lo = make_uint4(l[0], l[1], l[2], l[3]);
}
__device__ __forceinline__ const float* xgather_ptr(const float* X, int row, int k) {
    int t = k >> 7, d = k & 127, b = row >> 11, n = row & 2047;
    return X + ((long long)(b * 12 + t) * 2048 + n) * 128 + d;
}

// shared epilogue writer
__device__ __forceinline__ void epi_store(void* Cv, const float* bias, float acc[4][4][4],
    int bx, int by, long long bzsC, int ldc, int colstep, long long pC,
    float alpha, int epi, int omode, int t)
{
    const int lane = t & 31;
    const int wm = (t >> 7) * 64, wn = ((t >> 5) & 3) * 32;
    const int g = lane >> 2, tt = lane & 3;
    const long long rowBase = (long long)by * 128 + wm + g;
#pragma unroll
    for (int mf = 0; mf < 4; mf++) {
#pragma unroll
        for (int nf = 0; nf < 4; nf++) {
            const int nIdx = bx * 128 + wn + nf * 8 + 2 * tt;
            const int col = bx * colstep + wn + nf * 8 + 2 * tt;
            float2 bv = make_float2(0.f, 0.f);
            if (bias) bv = *(const float2*)(bias + nIdx);
            float x0 = epi_f(acc[mf][nf][0] * alpha + bv.x, epi);
            float y0 = epi_f(acc[mf][nf][1] * alpha + bv.y, epi);
            float x1 = epi_f(acc[mf][nf][2] * alpha + bv.x, epi);
            float y1 = epi_f(acc[mf][nf][3] * alpha + bv.y, epi);
            const long long r0 = (rowBase + mf * 16) * ldc + col;
            if (omode == 0) {
                float* C = (float*)Cv + bzsC;
                *(float2*)(C + r0) = make_float2(x0, y0);
                *(float2*)(C + r0 + 8LL * ldc) = make_float2(x1, y1);
            } else {
                bf16* Ch = (bf16*)Cv + bzsC;
                bf16* Cl = Ch + pC;
                uint32_t h, l;
                split2(x0, y0, h, l);
                *(uint32_t*)(Ch + r0) = h; *(uint32_t*)(Cl + r0) = l;
                split2(x1, y1, h, l);
                *(uint32_t*)(Ch + r0 + 8LL * ldc) = h; *(uint32_t*)(Cl + r0 + 8LL * ldc) = l;
            }
        }
    }
}

// ===== plane-input GEMM: C = epi(alpha*A@B^T+bias), A/B pre-split bf16 planes =====
__global__ void __launch_bounds__(256, 2)
gemm_pl(const bf16* __restrict__ Ah, const bf16* __restrict__ Bh,
        const float* __restrict__ bias, void* __restrict__ Cv,
        int K, int lda, int ldb, int ldc, int colstep, float alpha, int epi, int omode,
        long long pA, long long pB, long long pC,
        long long sA, long long sB, long long sC)
{
    extern __shared__ __align__(16) char smc[];
    const int t = threadIdx.x;
    const int bx = blockIdx.x, by = blockIdx.y, bz = blockIdx.z;
    const int lane = t & 31;
    const uint32_t smemBase = (uint32_t)__cvta_generic_to_shared(smc);

    const int lr2 = t >> 1, hf = t & 1, s7b = lr2 & 7;
    const bf16* Agh = Ah + bz * sA + (long long)(by * 128 + lr2) * lda;
    const bf16* Agl = Agh + pA;
    const bf16* Bgh = Bh + bz * sB + (long long)(bx * 128 + lr2) * ldb;
    const bf16* Bgl = Bgh + pB;
    const uint32_t rowb = smemBase + (uint32_t)lr2 * 128;

    const int sub = lane >> 3, l7 = lane & 7;
    const int wm = (t >> 7) * 64, wn = ((t >> 5) & 3) * 32;
    const int aRowOff = wm + l7 + ((sub & 1) << 3);
    const int aSel = sub >> 1;
    const int bRowOff = wn + l7 + ((sub >> 1) << 3);
    const int bSel = sub & 1;

    float acc[4][4][4];
#pragma unroll
    for (int i = 0; i < 4; i++)
#pragma unroll
        for (int j = 0; j < 4; j++)
#pragma unroll
            for (int q = 0; q < 4; q++) acc[i][j][q] = 0.f;

    const int nk = K >> 5;
#define ISSUE(S) do { \
    const uint32_t sb = rowb + (uint32_t)((S) & 1) * 32768u; \
    const int k0 = (S) * 32; \
    _Pragma("unroll") \
    for (int j = 0; j < 2; j++) { \
        int u = hf * 2 + j; \
        cpa16(sb + (uint32_t)((u ^ s7b) << 4), Agh + k0 + u * 8); \
        cpa16(sb + (uint32_t)(((u + 4) ^ s7b) << 4), Agl + k0 + u * 8); \
        cpa16(sb + 16384u + (uint32_t)((u ^ s7b) << 4), Bgh + k0 + u * 8); \
        cpa16(sb + 16384u + (uint32_t)(((u + 4) ^ s7b) << 4), Bgl + k0 + u * 8); \
    } \
    asm volatile("cp.async.commit_group;"); \
} while (0)

    ISSUE(0);
    for (int s = 0; s < nk; s++) {
        const bool more = (s + 1) < nk;
        if (more) ISSUE(s + 1);
        if (more) asm volatile("cp.async.wait_group 1;");
        else      asm volatile("cp.async.wait_group 0;");
        __syncthreads();
        const uint32_t stg = smemBase + (uint32_t)(s & 1) * 32768u;
#pragma unroll
        for (int kh = 0; kh < 2; kh++) {
            uint32_t ah[4][4], al[4][4], bh[4][2], bl[4][2];
#pragma unroll
            for (int mf = 0; mf < 4; mf++) {
                const uint32_t rb = stg + (uint32_t)(aRowOff + mf * 16) * 128;
                const int u0 = 2 * kh + aSel;
                ldsm4(ah[mf][0], ah[mf][1], ah[mf][2], ah[mf][3], rb + ((u0 ^ l7) << 4));
                ldsm4(al[mf][0], al[mf][1], al[mf][2], al[mf][3], rb + (((u0 + 4) ^ l7) << 4));
            }
#pragma unroll
            for (int np = 0; np < 2; np++) {
                const uint32_t rb = stg + 16384 + (uint32_t)(bRowOff + np * 16) * 128;
                const int u0 = 2 * kh + bSel;
                uint32_t r0, r1, r2, r3;
                ldsm4(r0, r1, r2, r3, rb + ((u0 ^ l7) << 4));
                bh[np*2][0] = r0; bh[np*2][1] = r1; bh[np*2+1][0] = r2; bh[np*2+1][1] = r3;
                ldsm4(r0, r1, r2, r3, rb + (((u0 + 4) ^ l7) << 4));
                bl[np*2][0] = r0; bl[np*2][1] = r1; bl[np*2+1][0] = r2; bl[np*2+1][1] = r3;
            }
#pragma unroll
            for (int mf = 0; mf < 4; mf++)
#pragma unroll
                for (int nf = 0; nf < 4; nf++) {
                    mma_bf16(acc[mf][nf], ah[mf], bh[nf]);
                    mma_bf16(acc[mf][nf], ah[mf], bl[nf]);
                    mma_bf16(acc[mf][nf], al[mf], bh[nf]);
                }
        }
        __syncthreads();
    }
#undef ISSUE
    epi_store(Cv, bias, acc, bx, by, (long long)bz * sC, ldc, colstep, pC, alpha, epi, omode, t);
}

// ===== f32-input GEMM (x-gather); used only for conv_down G1 =====
__global__ void __launch_bounds__(256)
gemm_f32(const float* __restrict__ A, const float* __restrict__ B,
         const float* __restrict__ bias, void* __restrict__ Cv,
         int K, int ldb, int ldc, int colstep, float alpha, int epi, int omode, long long pC)
{
    extern __shared__ __align__(16) uint4 sm[];
    const int t = threadIdx.x;
    const int bx = blockIdx.x, by = blockIdx.y;
    const int lane = t & 31;

    const int lr = t >> 2, lc = t & 3, s7 = lr & 7;
    const float* Bg0 = B + (long long)(bx * 128 + lr) * ldb + lc * 8;
    const float* Bg1 = Bg0 + (long long)64 * ldb;

    const int sub = lane >> 3, l7 = lane & 7;
    const int wm = (t >> 7) * 64, wn = ((t >> 5) & 3) * 32;
    const int aRowOff = wm + l7 + ((sub & 1) << 3);
    const int aSel = sub >> 1;
    const int bRowOff = wn + l7 + ((sub >> 1) << 3);
    const int bSel = sub & 1;
    const uint32_t smemBase = (uint32_t)__cvta_generic_to_shared(sm);

    float acc[4][4][4];
#pragma unroll
    for (int i = 0; i < 4; i++)
#pragma unroll
        for (int j = 0; j < 4; j++)
#pragma unroll
            for (int q = 0; q < 4; q++) acc[i][j][q] = 0.f;

    const int nk = K >> 5;
    {
        const float* pa0 = xgather_ptr(A, by*128 + lr, lc*8);
        const float* pa1 = xgather_ptr(A, by*128 + lr + 64, lc*8);
        uint4 hi, lo;
        uint4* bA0 = sm + lr * 8;        uint4* bA1 = bA0 + 512;
        uint4* bB0 = sm + 1024 + lr * 8; uint4* bB1 = bB0 + 512;
        split_pack(*(const float4*)pa0, *(const float4*)(pa0+4), hi, lo);
        bA0[lc ^ s7] = hi; bA0[(lc+4) ^ s7] = lo;
        split_pack(*(const float4*)pa1, *(const float4*)(pa1+4), hi, lo);
        bA1[lc ^ s7] = hi; bA1[(lc+4) ^ s7] = lo;
        split_pack(*(const float4*)Bg0, *(const float4*)(Bg0+4), hi, lo);
        bB0[lc ^ s7] = hi; bB0[(lc+4) ^ s7] = lo;
        split_pack(*(const float4*)Bg1, *(const float4*)(Bg1+4), hi, lo);
        bB1[lc ^ s7] = hi; bB1[(lc+4) ^ s7] = lo;
    }
    __syncthreads();

    for (int s = 0; s < nk; s++) {
        float4 a00, a01, a10, a11, b00, b01, b10, b11;
        const bool more = (s + 1) < nk;
        if (more) {
            const float* pa0 = xgather_ptr(A, by*128 + lr, (s+1)*32 + lc*8);
            const float* pa1 = xgather_ptr(A, by*128 + lr + 64, (s+1)*32 + lc*8);
            const float* pb0 = Bg0 + (s+1)*32; const float* pb1 = Bg1 + (s+1)*32;
            a00 = *(const float4*)pa0; a01 = *(const float4*)(pa0+4);
            a10 = *(const float4*)pa1; a11 = *(const float4*)(pa1+4);
            b00 = *(const float4*)pb0; b01 = *(const float4*)(pb0+4);
            b10 = *(const float4*)pb1; b11 = *(const float4*)(pb1+4);
        }
        const uint32_t stg = smemBase + (uint32_t)(s & 1) * 32768u;
#pragma unroll
        for (int kh = 0; kh < 2; kh++) {
            uint32_t ah[4][4], al[4][4], bh[4][2], bl[4][2];
#pragma unroll
            for (int mf = 0; mf < 4; mf++) {
                const uint32_t rb = stg + (uint32_t)(aRowOff + mf * 16) * 128;
                const int u0 = 2 * kh + aSel;
                ldsm4(ah[mf][0], ah[mf][1], ah[mf][2], ah[mf][3], rb + ((u0 ^ l7) << 4));
                ldsm4(al[mf][0], al[mf][1], al[mf][2], al[mf][3], rb + (((u0 + 4) ^ l7) << 4));
            }
#pragma unroll
            for (int np = 0; np < 2; np++) {
                const uint32_t rb = stg + 16384 + (uint32_t)(bRowOff + np * 16) * 128;
                const int u0 = 2 * kh + bSel;
                uint32_t r0, r1, r2, r3;
                ldsm4(r0, r1, r2, r3, rb + ((u0 ^ l7) << 4));
                bh[np*2][0] = r0; bh[np*2][1] = r1; bh[np*2+1][0] = r2; bh[np*2+1][1] = r3;
                ldsm4(r0, r1, r2, r3, rb + (((u0 + 4) ^ l7) << 4));
                bl[np*2][0] = r0; bl[np*2][1] = r1; bl[np*2+1][0] = r2; bl[np*2+1][1] = r3;
            }
#pragma unroll
            for (int mf = 0; mf < 4; mf++)
#pragma unroll
                for (int nf = 0; nf < 4; nf++) {
                    mma_bf16(acc[mf][nf], ah[mf], bh[nf]);
                    mma_bf16(acc[mf][nf], ah[mf], bl[nf]);
                    mma_bf16(acc[mf][nf], al[mf], bh[nf]);
                }
        }
        if (more) {
            const uint32_t ns = (uint32_t)((s + 1) & 1);
            uint4 hi, lo;
            uint4* bA0 = sm + ns*2048 + lr * 8;        uint4* bA1 = bA0 + 512;
            uint4* bB0 = sm + ns*2048 + 1024 + lr * 8; uint4* bB1 = bB0 + 512;
            split_pack(a00, a01, hi, lo); bA0[lc ^ s7] = hi; bA0[(lc+4) ^ s7] = lo;
            split_pack(a10, a11, hi, lo); bA1[lc ^ s7] = hi; bA1[(lc+4) ^ s7] = lo;
            split_pack(b00, b01, hi, lo); bB0[lc ^ s7] = hi; bB0[(lc+4) ^ s7] = lo;
            split_pack(b10, b11, hi, lo); bB1[lc ^ s7] = hi; bB1[(lc+4) ^ s7] = lo;
        }
        __syncthreads();
    }
    epi_store(Cv, bias, acc, bx, by, 0, ldc, colstep, pC, alpha, epi, omode, t);
}

// ===== producers / prep =====
__global__ void wqkv_fold(const float* __restrict__ Wq, const float* __restrict__ bq,
                          const float* __restrict__ Wk, const float* __restrict__ bk,
                          const float* __restrict__ Wv, const float* __restrict__ bv,
                          const float* __restrict__ Wd2, const float* __restrict__ bd2,
                          bf16* __restrict__ Wh, float* __restrict__ BQKV)
{
    int i = blockIdx.x, j = threadIdx.x;
    const float* row = (i < 128) ? Wq + i * 128 : (i < 256) ? Wk + (i - 128) * 128 : Wv + (i - 256) * 128;
    float bo = (i < 128) ? bq[i] : (i < 256) ? bk[i - 128] : bv[i - 256];
    float acc = 0.f, accb = 0.f;
    for (int c = 0; c < 128; c++) {
        float w = row[c];
        acc += w * Wd2[c * 128 + j];
        accb += w * bd2[c];
    }
    bf16 h, l; split1(acc, h, l);
    Wh[i * 128 + j] = h; Wh[49152 + i * 128 + j] = l;
    if (j == 0) BQKV[i] = accb + bo;
}

__global__ void build_w1(const float* __restrict__ Wr1, const float* __restrict__ br1,
                         const float* __restrict__ Wi1, const float* __restrict__ bi1,
                         bf16* __restrict__ W1A, float* __restrict__ b1a,
                         bf16* __restrict__ W1B, float* __restrict__ b1b)
{
    int i = blockIdx.x * 256 + threadIdx.x;
    int r = i >> 7, c = i & 127;
    float va = (r < 128) ? Wr1[r * 128 + c] : Wi1[(r - 128) * 128 + c];
    float vb = (r < 128) ? Wi1[r * 128 + c] : Wr1[(r - 128) * 128 + c];
    bf16 h, l;
    split1(va, h, l); W1A[i] = h; W1A[32768 + i] = l;
    split1(vb, h, l); W1B[i] = h; W1B[32768 + i] = l;
    if (i < 256) {
        b1a[i] = (i < 128) ? br1[i] : bi1[i - 128];
        b1b[i] = (i < 128) ? bi1[i] : br1[i - 128];
    }
}

__global__ void build_wcat(const float* __restrict__ Wr2, const float* __restrict__ br2,
                           const float* __restrict__ Wi2, const float* __restrict__ bi2,
                           bf16* __restrict__ WCR, float* __restrict__ bcr,
                           bf16* __restrict__ WCI, float* __restrict__ bci)
{
    int i = blockIdx.x * 256 + threadIdx.x;
    int n = i >> 8, k = i & 255;
    float vr, vi;
    if (k < 128) { vr = Wr2[n * 128 + k];        vi = Wi2[n * 128 + k]; }
    else         { vr = -Wi2[n * 128 + k - 128]; vi = Wr2[n * 128 + k - 128]; }
    bf16 h, l;
    split1(vr, h, l); WCR[i] = h; WCR[32768 + i] = l;
    split1(vi, h, l); WCI[i] = h; WCI[32768 + i] = l;
    if (i < 128) { bcr[i] = br2[i] - bi2[i]; bci[i] = bi2[i] + br2[i]; }
}

__global__ void wconv(const float* __restrict__ W, bf16* __restrict__ Wp, int n, int plane) {
    int i = blockIdx.x * 256 + threadIdx.x;
    if (i < n) { bf16 h, l; split1(W[i], h, l); Wp[i] = h; Wp[plane + i] = l; }
}

__global__ void transpose_v(const bf16* __restrict__ Qh, const bf16* __restrict__ Ql,
                            bf16* __restrict__ VTh, bf16* __restrict__ VTl)
{
    __shared__ uint32_t tile[32][33];
    int b = blockIdx.z, n0 = blockIdx.x * 32, d0 = blockIdx.y * 32;
    int tx = threadIdx.x & 31, ty = threadIdx.x >> 5;
#pragma unroll
    for (int i = 0; i < 32; i += 8) {
        long long idx = ((long long)b * 2048 + n0 + ty + i) * 384 + 256 + d0 + tx;
        tile[ty + i][tx] = (uint32_t)__bfloat16_as_ushort(Qh[idx])
                         | ((uint32_t)__bfloat16_as_ushort(Ql[idx]) << 16);
    }
    __syncthreads();
#pragma unroll
    for (int i = 0; i < 32; i += 8) {
        uint32_t p = tile[tx][ty + i];
        long long o = (long long)b * 262144 + (long long)(d0 + ty + i) * 2048 + n0 + tx;
        VTh[o] = __ushort_as_bfloat16((unsigned short)(p & 0xffff));
        VTl[o] = __ushort_as_bfloat16((unsigned short)(p >> 16));
    }
}

__global__ void softmax2048(const float* __restrict__ S, bf16* __restrict__ Sh, bf16* __restrict__ Sl) {
    const float* row = S + (long long)blockIdx.x * 2048;
    long long obase = (long long)blockIdx.x * 2048;
    int t = threadIdx.x;
    float v[8], mx = -3.4e38f;
#pragma unroll
    for (int i = 0; i < 8; i++) { v[i] = row[t + (i << 8)]; mx = fmaxf(mx, v[i]); }
    __shared__ float red[8];
#pragma unroll
    for (int o = 16; o; o >>= 1) mx = fmaxf(mx, __shfl_xor_sync(0xffffffffu, mx, o));
    if ((t & 31) == 0) red[t >> 5] = mx;
    __syncthreads();
    mx = red[0];
#pragma unroll
    for (int i = 1; i < 8; i++) mx = fmaxf(mx, red[i]);
    float s = 0.f;
#pragma unroll
    for (int i = 0; i < 8; i++) { v[i] = __expf(v[i] - mx); s += v[i]; }
#pragma unroll
    for (int o = 16; o; o >>= 1) s += __shfl_xor_sync(0xffffffffu, s, o);
    __syncthreads();
    if ((t & 31) == 0) red[t >> 5] = s;
    __syncthreads();
    s = 0.f;
#pragma unroll
    for (int i = 0; i < 8; i++) s += red[i];
    float inv = 1.f / s;
#pragma unroll
    for (int i = 0; i < 8; i++) {
        bf16 h, l; split1(v[i] * inv, h, l);
        Sh[obase + t + (i << 8)] = h; Sl[obase + t + (i << 8)] = l;
    }
}

__global__ void ln_dft(const float* __restrict__ ON, const float* __restrict__ x,
                       const float* __restrict__ gamma, const float* __restrict__ beta,
                       bf16* __restrict__ Rh, bf16* __restrict__ Rl,
                       bf16* __restrict__ Ih, bf16* __restrict__ Il)
{
    int bn = blockIdx.x;
    int d = threadIdx.x;
    int b = bn >> 11, n = bn & 2047;
    float v[12];
    const float* onp = ON + (long long)bn * 1536 + d;
    const float* xp = x + ((long long)(b * 12) * 2048 + n) * 128 + d;
#pragma unroll
    for (int t = 0; t < 12; t++) v[t] = onp[t * 128] + xp[(long long)t * 262144];

    __shared__ float sred[12][4], qred[12][4];
    int w = d >> 5, lane = d & 31;
#pragma unroll
    for (int t = 0; t < 12; t++) {
        float s = v[t], q = v[t] * v[t];
#pragma unroll
        for (int o = 16; o; o >>= 1) {
            s += __shfl_xor_sync(0xffffffffu, s, o);
            q += __shfl_xor_sync(0xffffffffu, q, o);
        }
        if (lane == 0) { sred[t][w] = s; qred[t][w] = q; }
    }
    __syncthreads();
    float g = gamma[d], be = beta[d];
#pragma unroll
    for (int t = 0; t < 12; t++) {
        float s = sred[t][0] + sred[t][1] + sred[t][2] + sred[t][3];
        float q = qred[t][0] + qred[t][1] + qred[t][2] + qred[t][3];
        float mu = s * (1.f / 128.f);
        float var = q * (1.f / 128.f) - mu * mu;
        v[t] = (v[t] - mu) * rsqrtf(var + 1e-5f) * g + be;
    }
    const float CT[12] = {1.f, 0.8660254037844386f, 0.5f, 0.f, -0.5f, -0.8660254037844386f,
                          -1.f, -0.8660254037844386f, -0.5f, 0.f, 0.5f, 0.8660254037844386f};
    const float ST[12] = {0.f, 0.5f, 0.8660254037844386f, 1.f, 0.8660254037844386f, 0.5f,
                          0.f, -0.5f, -0.8660254037844386f, -1.f, -0.8660254037844386f, -0.5f};
#pragma unroll
    for (int f = 0; f < 7; f++) {
        float sr = 0.f, si = 0.f;
#pragma unroll
        for (int t = 0; t < 12; t++) {
            int k = (f * t) % 12;
            sr += v[t] * CT[k];
            si -= v[t] * ST[k];
        }
        long long o = ((long long)(b * 7 + f)) * 262144 + n * 128 + d;
        bf16 h, l;
        split1(sr, h, l); Rh[o] = h; Rl[o] = l;
        split1(si, h, l); Ih[o] = h; Il[o] = l;
    }
}

__global__ void irfft12(const float* __restrict__ HR, const float* __restrict__ HI,
                        const float* __restrict__ x, float* __restrict__ out)
{
    int idx = blockIdx.x * 256 + threadIdx.x;
    int b = idx >> 18, nd = idx & 262143;
    float hr[7], hi[7];
#pragma unroll
    for (int f = 0; f < 7; f++) {
        long long o = ((long long)b * 7 + f) * 262144 + nd;
        hr[f] = HR[o]; hi[f] = HI[o];
    }
    const float CT[12] = {1.f, 0.8660254037844386f, 0.5f, 0.f, -0.5f, -0.8660254037844386f,
                          -1.f, -0.8660254037844386f, -0.5f, 0.f, 0.5f, 0.8660254037844386f};
    const float ST[12] = {0.f, 0.5f, 0.8660254037844386f, 1.f, 0.8660254037844386f, 0.5f,
                          0.f, -0.5f, -0.8660254037844386f, -1.f, -0.8660254037844386f, -0.5f};
#pragma unroll
    for (int t = 0; t < 12; t++) {
        float acc = hr[0] + ((t & 1) ? -hr[6] : hr[6]);
#pragma unroll
        for (int f = 1; f < 6; f++) {
            int k = (f * t) % 12;
            acc += 2.f * (hr[f] * CT[k] - hi[f] * ST[k]);
        }
        long long o = ((long long)b * 12 + t) * 262144 + nd;
        out[o] = x[o] + acc * (1.f / 12.f);
    }
}

extern "C" void kernel_launch(void* const* d_in, const int* in_sizes, int n_in,
                              void* d_out, int out_size)
{
    const float* x   = (const float*)d_in[0];
    const float* Wd1 = (const float*)d_in[1];  const float* bd1 = (const float*)d_in[2];
    const float* Wd2 = (const float*)d_in[3];  const float* bd2 = (const float*)d_in[4];
    const float* Wq  = (const float*)d_in[5];  const float* bq  = (const float*)d_in[6];
    const float* Wk  = (const float*)d_in[7];  const float* bk  = (const float*)d_in[8];
    const float* Wv  = (const float*)d_in[9];  const float* bv  = (const float*)d_in[10];
    const float* Wu1 = (const float*)d_in[11]; const float* bu1 = (const float*)d_in[12];
    const float* Wu2 = (const float*)d_in[13]; const float* bu2 = (const float*)d_in[14];
    const float* gamma = (const float*)d_in[15];
    const float* beta  = (const float*)d_in[16];
    const float* Wr1 = (const float*)d_in[17]; const float* br1 = (const float*)d_in[18];
    const float* Wr2 = (const float*)d_in[19]; const float* br2 = (const float*)d_in[20];
    const float* Wi1 = (const float*)d_in[21]; const float* bi1 = (const float*)d_in[22];
    const float* Wi2 = (const float*)d_in[23]; const float* bi2 = (const float*)d_in[24];
    float* out = (float*)d_out;

    float* A = nullptr;
    cudaGetSymbolAddress((void**)&A, g_arena);

    float* S   = A + OFF_S;
    bf16* Uh   = (bf16*)(A + OFF_S);
    bf16* Sh   = (bf16*)(A + OFF_SP);   bf16* Sl = Sh + 67108864LL;
    float* ON  = A + OFF_SP;
    bf16* H1h  = (bf16*)(A + OFF_H1P);
    bf16* QKVh = (bf16*)(A + OFF_QKVP); bf16* QKVl = QKVh + 12582912LL;
    bf16* VTh  = (bf16*)(A + OFF_VTP);  bf16* VTl = VTh + 4194304LL;
    bf16* Oh   = (bf16*)(A + OFF_OP);
    bf16* Rh   = (bf16*)(A + OFF_REP);  bf16* Rl = Rh + 29360128LL;
    bf16* Ih   = (bf16*)(A + OFF_IMP);  bf16* Il = Ih + 29360128LL;
    bf16* H2h  = (bf16*)(A + OFF_H2P);
    float* HR  = A + OFF_REP;
    float* HI  = A + OFF_IMP;
    bf16* WQKVh = (bf16*)(A + OFF_WQKVP); float* BQKV = A + OFF_BQKV;
    bf16* WU1h  = (bf16*)(A + OFF_WU1P);
    bf16* WU2h  = (bf16*)(A + OFF_WU2P);
    bf16* W1Ah  = (bf16*)(A + OFF_W1AP);  bf16* W1Bh = (bf16*)(A + OFF_W1BP);
    float* B1A  = A + OFF_B1A;            float* B1B = A + OFF_B1B;
    bf16* WCRh  = (bf16*)(A + OFF_WCRP);  bf16* WCIh = (bf16*)(A + OFF_WCIP);
    float* BCR  = A + OFF_BCR;            float* BCI = A + OFF_BCI;

    cudaFuncSetAttribute(gemm_pl, cudaFuncAttributeMaxDynamicSharedMemorySize, 65536);
    cudaFuncSetAttribute(gemm_f32, cudaFuncAttributeMaxDynamicSharedMemorySize, 65536);

    // weight prep
    wqkv_fold<<<384, 128>>>(Wq, bq, Wk, bk, Wv, bv, Wd2, bd2, WQKVh, BQKV);
    build_w1<<<128, 256>>>(Wr1, br1, Wi1, bi1, W1Ah, B1A, W1Bh, B1B);
    build_wcat<<<128, 256>>>(Wr2, br2, Wi2, bi2, WCRh, BCR, WCIh, BCI);
    wconv<<<768, 256>>>(Wu1, WU1h, 196608, 196608);
    wconv<<<9216, 256>>>(Wu2, WU2h, 2359296, 2359296);

    // conv_down G1 (x gather, f32 in) -> H1 planes
    gemm_f32<<<dim3(1, 256, 1), 256, 65536>>>(x, Wd1, bd1, (void*)H1h,
        1536, 1536, 128, 128, 1.f, 1, 1, 4194304LL);
    // QKV (folded) -> QKV planes
    gemm_pl<<<dim3(3, 256, 1), 256, 65536>>>(H1h, WQKVh, BQKV, (void*)QKVh,
        128, 128, 128, 384, 128, 1.f, 0, 1, 4194304LL, 49152LL, 12582912LL, 0, 0, 0);
    // QK^T -> S f32
    gemm_pl<<<dim3(16, 16, 16), 256, 65536>>>(QKVh, QKVh + 128, nullptr, (void*)S,
        128, 384, 384, 2048, 128, 0.125f, 0, 0, 12582912LL, 12582912LL, 0,
        786432LL, 786432LL, 4194304LL);
    softmax2048<<<32768, 256>>>(S, Sh, Sl);
    transpose_v<<<dim3(64, 4, 16), 256>>>(QKVh, QKVl, VTh, VTl);
    // S@V -> O planes
    gemm_pl<<<dim3(1, 16, 16), 256, 65536>>>(Sh, VTh, nullptr, (void*)Oh,
        2048, 2048, 2048, 128, 128, 1.f, 0, 1, 67108864LL, 4194304LL, 4194304LL,
        4194304LL, 262144LL, 262144LL);
    // conv_up
    gemm_pl<<<dim3(12, 256, 1), 256, 65536>>>(Oh, WU1h, bu1, (void*)Uh,
        128, 128, 128, 1536, 128, 1.f, 1, 1, 4194304LL, 196608LL, 50331648LL, 0, 0, 0);
    gemm_pl<<<dim3(12, 256, 1), 256, 65536>>>(Uh, WU2h, bu2, (void*)ON,
        1536, 1536, 1536, 1536, 128, 1.f, 0, 0, 50331648LL, 2359296LL, 0, 0, 0, 0);
    // residual + LN + rfft -> RE/IM planes
    ln_dft<<<32768, 128>>>(ON, x, gamma, beta, Rh, Rl, Ih, Il);
    // FFT MLP layer 1 (gelu) -> H2 planes
    gemm_pl<<<dim3(2, 1792, 1), 256, 65536>>>(Rh, W1Ah, B1A, (void*)H2h,
        128, 128, 128, 512, 256, 1.f, 2, 1, 29360128LL, 32768LL, 117440512LL, 0, 0, 0);
    gemm_pl<<<dim3(2, 1792, 1), 256, 65536>>>(Ih, W1Bh, B1B, (void*)(H2h + 128),
        128, 128, 128, 512, 256, 1.f, 2, 1, 29360128LL, 32768LL, 117440512LL, 0, 0, 0);
    // FFT MLP layer 2 -> HR/HI f32
    gemm_pl<<<dim3(1, 1792, 1), 256, 65536>>>(H2h, WCRh, BCR, (void*)HR,
        256, 512, 256, 128, 128, 1.f, 0, 0, 117440512LL, 32768LL, 0, 0, 0, 0);
    gemm_pl<<<dim3(1, 1792, 1), 256, 65536>>>(H2h + 256, WCIh, BCI, (void*)HI,
        256, 512, 256, 128, 128, 1.f, 0, 0, 117440512LL, 32768LL, 0, 0, 0, 0);
    // irfft + residual
    irfft12<<<16384, 256>>>(HR, HI, x, out);
}